// round 13
// baseline (speedup 1.0000x reference)
#include <cuda_runtime.h>
#include <cuda_bf16.h>
#include <cstdint>

#define Bb   128
#define Tt   1024
#define Dd   256
#define Hh   256
#define BT   (Bb * Tt)

__device__ float g_xz[(size_t)BT * Hh];
__device__ float g_xr[(size_t)BT * Hh];
__device__ float g_xh[(size_t)BT * Hh];

__device__ __forceinline__ float2 ffma2(float2 a, float2 b, float2 c) {
    float2 d;
    asm("fma.rn.f32x2 %0, %1, %2, %3;"
        : "=l"(*reinterpret_cast<unsigned long long*>(&d))
        : "l"(*reinterpret_cast<const unsigned long long*>(&a)),
          "l"(*reinterpret_cast<const unsigned long long*>(&b)),
          "l"(*reinterpret_cast<const unsigned long long*>(&c)));
    return d;
}

__device__ __forceinline__ float hsig(float x) {
    return fminf(fmaxf(fmaf(x, 0.2f, 0.5f), 0.0f), 1.0f);
}

__device__ __forceinline__ uint32_t smem_u32(const void* p) {
    uint32_t a;
    asm("{ .reg .u64 t; cvta.to.shared.u64 t, %1; cvt.u32.u64 %0, t; }"
        : "=r"(a) : "l"(p));
    return a;
}

__device__ __forceinline__ void st_remote_f2(uint32_t laddr, int rank, float2 v) {
    uint32_t raddr;
    asm volatile("mapa.shared::cluster.u32 %0, %1, %2;"
                 : "=r"(raddr) : "r"(laddr), "r"(rank));
    asm volatile("st.shared::cluster.v2.f32 [%0], {%1, %2};"
                 :: "r"(raddr), "f"(v.x), "f"(v.y) : "memory");
}

__device__ __forceinline__ void cluster_sync_() {
    asm volatile("barrier.cluster.arrive.aligned;" ::: "memory");
    asm volatile("barrier.cluster.wait.aligned;" ::: "memory");
}

__device__ __forceinline__ uint32_t ctarank_() {
    uint32_t r;
    asm("mov.u32 %0, %%cluster_ctarank;" : "=r"(r));
    return r;
}

__device__ __forceinline__ void mbar_arrive_remote(uint32_t laddr, int rank) {
    uint32_t raddr;
    asm volatile("mapa.shared::cluster.u32 %0, %1, %2;"
                 : "=r"(raddr) : "r"(laddr), "r"(rank));
    asm volatile("mbarrier.arrive.release.cluster.shared::cluster.b64 _, [%0];"
                 :: "r"(raddr) : "memory");
}

__device__ __forceinline__ void mbar_wait_parity(uint32_t addr, uint32_t parity) {
    asm volatile(
        "{\n\t"
        ".reg .pred P;\n\t"
        "WL_%=:\n\t"
        "mbarrier.try_wait.parity.acquire.cluster.shared::cta.b64 P, [%0], %1, 0x989680;\n\t"
        "@!P bra WL_%=;\n\t"
        "}"
        :: "r"(addr), "r"(parity) : "memory");
}

// ---------------------------------------------------------------------------
// HMMA projection (unchanged from R9/R11 — banked at ~692us)
// ---------------------------------------------------------------------------
#define RS     264
#define PA_HI  0
#define PA_LO  67584
#define PB_HI  135168
#define PB_LO  168960
#define PROJ_SMEM_BYTES 202752

__device__ __forceinline__ void ldsm_x4(uint32_t addr, uint32_t* r) {
    asm volatile("ldmatrix.sync.aligned.m8n8.x4.shared.b16 {%0,%1,%2,%3}, [%4];"
                 : "=r"(r[0]), "=r"(r[1]), "=r"(r[2]), "=r"(r[3]) : "r"(addr));
}
__device__ __forceinline__ void ldsm_x2(uint32_t addr, uint32_t* r) {
    asm volatile("ldmatrix.sync.aligned.m8n8.x2.shared.b16 {%0,%1}, [%2];"
                 : "=r"(r[0]), "=r"(r[1]) : "r"(addr));
}
__device__ __forceinline__ void mma_bf16(float* c, const uint32_t* a, const uint32_t* b) {
    asm volatile(
        "mma.sync.aligned.m16n8k16.row.col.f32.bf16.bf16.f32 "
        "{%0,%1,%2,%3}, {%4,%5,%6,%7}, {%8,%9}, {%0,%1,%2,%3};"
        : "+f"(c[0]), "+f"(c[1]), "+f"(c[2]), "+f"(c[3])
        : "r"(a[0]), "r"(a[1]), "r"(a[2]), "r"(a[3]), "r"(b[0]), "r"(b[1]));
}

__global__ __launch_bounds__(256, 1) void proj_mma_kernel(
    const float* __restrict__ x,
    const float* __restrict__ Wz, const float* __restrict__ Wr,
    const float* __restrict__ Wh,
    const float* __restrict__ bz, const float* __restrict__ br,
    const float* __restrict__ bh)
{
    extern __shared__ char dsm[];
    const uint32_t sbase = smem_u32(dsm);

    const int tid  = threadIdx.x;
    const int wid  = tid >> 5;
    const int lane = tid & 31;
    const int row0 = blockIdx.x * 128;
    const int mg   = wid >> 1;
    const int ng   = wid & 1;

    for (int idx = tid; idx < 128 * 64; idx += 256) {
        int m = idx >> 6, kq = (idx & 63) << 2;
        float4 v = *reinterpret_cast<const float4*>(&x[(size_t)(row0 + m) * Dd + kq]);
        __nv_bfloat16 h0 = __float2bfloat16(v.x), h1 = __float2bfloat16(v.y);
        __nv_bfloat16 h2 = __float2bfloat16(v.z), h3 = __float2bfloat16(v.w);
        __nv_bfloat16 l0 = __float2bfloat16(v.x - __bfloat162float(h0));
        __nv_bfloat16 l1 = __float2bfloat16(v.y - __bfloat162float(h1));
        __nv_bfloat16 l2 = __float2bfloat16(v.z - __bfloat162float(h2));
        __nv_bfloat16 l3 = __float2bfloat16(v.w - __bfloat162float(h3));
        uint32_t off = (uint32_t)(m * RS + kq) * 2u;
        *reinterpret_cast<__nv_bfloat162*>(dsm + PA_HI + off)     = __halves2bfloat162(h0, h1);
        *reinterpret_cast<__nv_bfloat162*>(dsm + PA_HI + off + 4) = __halves2bfloat162(h2, h3);
        *reinterpret_cast<__nv_bfloat162*>(dsm + PA_LO + off)     = __halves2bfloat162(l0, l1);
        *reinterpret_cast<__nv_bfloat162*>(dsm + PA_LO + off + 4) = __halves2bfloat162(l2, l3);
    }

    const int arow = 32 * mg + (lane & 15);
    const int ako  = (lane >> 4) * 8;
    const uint32_t ah0 = sbase + PA_HI + (uint32_t)(arow * RS + ako) * 2u;
    const uint32_t ah1 = ah0 + (uint32_t)(16 * RS) * 2u;
    const uint32_t al0 = sbase + PA_LO + (uint32_t)(arow * RS + ako) * 2u;
    const uint32_t al1 = al0 + (uint32_t)(16 * RS) * 2u;

    const int nrow = 32 * ng + (lane & 7);
    const int bko  = (lane & 8) ? 8 : 0;
    const uint32_t bph = sbase + PB_HI + (uint32_t)(nrow * RS + bko) * 2u;
    const uint32_t bpl = sbase + PB_LO + (uint32_t)(nrow * RS + bko) * 2u;

    const int gid = lane >> 2;
    const int tig = lane & 3;

    for (int g = 0; g < 3; g++) {
        const float* W  = (g == 0) ? Wz : (g == 1) ? Wr : Wh;
        const float* bs = (g == 0) ? bz : (g == 1) ? br : bh;
        float* outp     = (g == 0) ? g_xz : (g == 1) ? g_xr : g_xh;

        for (int nc = 0; nc < 4; nc++) {
            const int n0 = nc * 64;
            __syncthreads();

            for (int idx = tid; idx < 64 * 128; idx += 256) {
                int k2 = idx >> 6;
                int n  = idx & 63;
                float w0 = W[(size_t)(2 * k2) * Hh + n0 + n];
                float w1 = W[(size_t)(2 * k2 + 1) * Hh + n0 + n];
                __nv_bfloat16 h0 = __float2bfloat16(w0);
                __nv_bfloat16 h1 = __float2bfloat16(w1);
                __nv_bfloat16 l0 = __float2bfloat16(w0 - __bfloat162float(h0));
                __nv_bfloat16 l1 = __float2bfloat16(w1 - __bfloat162float(h1));
                uint32_t off = (uint32_t)(n * RS + 2 * k2) * 2u;
                *reinterpret_cast<__nv_bfloat162*>(dsm + PB_HI + off) = __halves2bfloat162(h0, h1);
                *reinterpret_cast<__nv_bfloat162*>(dsm + PB_LO + off) = __halves2bfloat162(l0, l1);
            }
            __syncthreads();

            float acc[2][4][4];
#pragma unroll
            for (int mt = 0; mt < 2; mt++)
#pragma unroll
                for (int nt = 0; nt < 4; nt++)
#pragma unroll
                    for (int j = 0; j < 4; j++) acc[mt][nt][j] = 0.0f;

#pragma unroll 4
            for (int ks = 0; ks < 16; ks++) {
                const uint32_t ko = (uint32_t)ks * 32u;
                uint32_t afh[2][4], afl[2][4];
                ldsm_x4(ah0 + ko, afh[0]);
                ldsm_x4(ah1 + ko, afh[1]);
                ldsm_x4(al0 + ko, afl[0]);
                ldsm_x4(al1 + ko, afl[1]);
#pragma unroll
                for (int nt = 0; nt < 4; nt++) {
                    const uint32_t boff = (uint32_t)(nt * 8 * RS) * 2u + ko;
                    uint32_t bfh[2], bfl[2];
                    ldsm_x2(bph + boff, bfh);
                    ldsm_x2(bpl + boff, bfl);
#pragma unroll
                    for (int mt = 0; mt < 2; mt++) {
                        mma_bf16(acc[mt][nt], afh[mt], bfh);
                        mma_bf16(acc[mt][nt], afh[mt], bfl);
                        mma_bf16(acc[mt][nt], afl[mt], bfh);
                    }
                }
            }

#pragma unroll
            for (int mt = 0; mt < 2; mt++) {
                const int row = row0 + 32 * mg + 16 * mt + gid;
#pragma unroll
                for (int nt = 0; nt < 4; nt++) {
                    const int col = n0 + 32 * ng + 8 * nt + tig * 2;
                    float2 bv = *reinterpret_cast<const float2*>(&bs[col]);
                    float2 v0 = make_float2(acc[mt][nt][0] + bv.x, acc[mt][nt][1] + bv.y);
                    float2 v1 = make_float2(acc[mt][nt][2] + bv.x, acc[mt][nt][3] + bv.y);
                    *reinterpret_cast<float2*>(&outp[(size_t)row * Hh + col])       = v0;
                    *reinterpret_cast<float2*>(&outp[(size_t)(row + 8) * Hh + col]) = v1;
                }
            }
        }
    }
}

// ---------------------------------------------------------------------------
// Cluster scan R13: k-split flow with r->z->candidate sequencing.
// All three matvecs use the proven ksub=8 full-width structure (cg=tid>>3,
// k8=tid&7). Ur and Uz register-resident (8 float4 each), Uh in SMEM.
// Order per step:
//   A: r partials -> inbox_r -> arrive mb_r
//   B: z partials -> inbox_z[ph] -> arrive mb_z        (hides r flight)
//   C: (tid<256) wait mb_r [fast], reduce r, publish r*h; __syncthreads
//   D: candidate partials -> inbox_h -> arrive mb_h    (hides z flight)
//   E/F: (tid<256) wait mb_z [fast], zkeep; wait mb_h, reduce, update h
// inbox_z is parity double-buffered (its reads are not covered by the
// release/acquire chain that protects inbox_r / inbox_h).
// ---------------------------------------------------------------------------
#define UH_OFF   0                        // 16384 floats (64KB)
#define HT_OFF   16384                    // 288 floats, swz f(k)=4k+8((k>>4)&3)
#define RHT_OFF  (HT_OFF + 288)           // 288
#define INR_OFF  (RHT_OFF + 288)          // [src4][b4][cl64] = 1024
#define INZ_OFF  (INR_OFF + 1024)         // 2 x 1024 (parity buffers)
#define INH_OFF  (INZ_OFF + 2048)         // 1024
#define MBAR_OFF (INH_OFF + 1024)         // 3 mbars = 6 floats
#define SMEM_FLOATS (MBAR_OFF + 6)

__global__ void __cluster_dims__(4, 1, 1) __launch_bounds__(512, 1)
scan_cluster_kernel(const float* __restrict__ Uz, const float* __restrict__ Ur,
                    const float* __restrict__ Uh, float* __restrict__ out)
{
    extern __shared__ float sm[];
    const int tid  = threadIdx.x;
    const int lane = tid & 31;
    const int rank = (int)ctarank_();
    const int cluster_id = blockIdx.x >> 2;

    const uint32_t mbr = smem_u32(&sm[MBAR_OFF]);
    const uint32_t mbz = smem_u32(&sm[MBAR_OFF + 2]);
    const uint32_t mbh = smem_u32(&sm[MBAR_OFF + 4]);

    // ---- stage Uh k-slice (quad-rotated rows, proven layout) ----
    for (int i = tid; i < 64 * 64; i += 512) {
        int k = i >> 6, c = (i & 63) * 4;
        int cs = (c + ((k >> 3) & 7) * 4) & 255;
        *reinterpret_cast<float4*>(&sm[UH_OFF + k * 256 + cs]) =
            *reinterpret_cast<const float4*>(&Uh[(size_t)(64 * rank + k) * Hh + c]);
    }
    if (tid < 256) {
        int k = tid >> 2, b = tid & 3;
        sm[HT_OFF + k * 4 + ((k >> 4) & 3) * 8 + b] = 0.0f;
    }
    if (tid == 0) {
        asm volatile("mbarrier.init.shared.b64 [%0], %1;" :: "r"(mbr), "r"(16) : "memory");
        asm volatile("mbarrier.init.shared.b64 [%0], %1;" :: "r"(mbz), "r"(16) : "memory");
        asm volatile("mbarrier.init.shared.b64 [%0], %1;" :: "r"(mbh), "r"(16) : "memory");
    }

    // ---- matvec identity (shared by all three segments) ----
    const int cg   = tid >> 3;              // 0..63 col quad
    const int k8   = tid & 7;               // 8-k slice
    const int crot = (cg * 4 + k8 * 4) & 255;
    const int dst  = cg >> 4;               // warp-uniform dest CTA
    const int cl   = (cg & 15) * 4;
    const int hb   = HT_OFF  + 32 * k8 + 8 * (k8 >> 1);
    const int rhb  = RHT_OFF + 32 * k8 + 8 * (k8 >> 1);
    const uint32_t send_off =
        (uint32_t)(((rank * 4 + (k8 >> 1)) * 64 + cl + (k8 & 1) * 2) * 4);

    // register-resident Ur / Uz slices (8 k x 4 cols each)
    float4 UrR[8], UzR[8];
#pragma unroll
    for (int kk = 0; kk < 8; kk++) {
        UrR[kk] = *reinterpret_cast<const float4*>(
            &Ur[(size_t)(64 * rank + k8 * 8 + kk) * Hh + cg * 4]);
        UzR[kk] = *reinterpret_cast<const float4*>(
            &Uz[(size_t)(64 * rank + k8 * 8 + kk) * Hh + cg * 4]);
    }

    // ---- reducer identity (tid < 256) ----
    const int rb    = (tid >> 6) & 3;
    const int rcl   = tid & 63;
    const int rswz  = rcl * 4 + ((rcl >> 4) & 3) * 8;
    const int cglob = rank * 64 + rcl;
    const int bglob = cluster_id * 4 + rb;
    const size_t xbase = ((size_t)bglob * Tt) * Hh + cglob;

    const uint32_t inr_b = smem_u32(&sm[INR_OFF]);
    const uint32_t inz_b = smem_u32(&sm[INZ_OFF]);
    const uint32_t inh_b = smem_u32(&sm[INH_OFF]);

    float h_reg = 0.0f;

    __syncthreads();
    cluster_sync_();   // staging + mbar init visible cluster-wide

#pragma unroll 1
    for (int t = 0; t < Tt; t++) {
        const uint32_t ph = (uint32_t)(t & 1);

        float xzv = 0.f, xrv = 0.f, xhv = 0.f;
        if (tid < 256) {
            const size_t xoff = xbase + (size_t)t * Hh;
            xzv = g_xz[xoff]; xrv = g_xr[xoff]; xhv = g_xh[xoff];
        }

        float2 v[8];

        // ================= segment A: r matvec =================
#pragma unroll
        for (int j = 0; j < 8; j++) v[j] = make_float2(0.f, 0.f);
#pragma unroll
        for (int kk = 0; kk < 8; kk++) {
            float4 u  = UrR[kk];
            float4 h4 = *reinterpret_cast<const float4*>(&sm[hb + kk * 4]);
            float2 u01 = make_float2(u.x, u.y), u23 = make_float2(u.z, u.w);
            const float hv[4] = {h4.x, h4.y, h4.z, h4.w};
#pragma unroll
            for (int b = 0; b < 4; b++) {
                float2 h2 = make_float2(hv[b], hv[b]);
                v[2 * b]     = ffma2(u01, h2, v[2 * b]);
                v[2 * b + 1] = ffma2(u23, h2, v[2 * b + 1]);
            }
        }
        {
            // 8-lane reduce-scatter (xor4, xor2, xor1) -> fin (b=k8>>1, cp=k8&1)
            const bool h4b = (k8 >> 2) & 1;
#pragma unroll
            for (int j = 0; j < 4; j++) {
                float sx = h4b ? v[j].x : v[j + 4].x;
                float sy = h4b ? v[j].y : v[j + 4].y;
                float rx = __shfl_xor_sync(0xffffffffu, sx, 4);
                float ry = __shfl_xor_sync(0xffffffffu, sy, 4);
                if (h4b) { v[j + 4].x += rx; v[j + 4].y += ry; }
                else     { v[j].x     += rx; v[j].y     += ry; }
            }
            float2 w[4];
#pragma unroll
            for (int j = 0; j < 4; j++) {
                w[j].x = h4b ? v[j + 4].x : v[j].x;
                w[j].y = h4b ? v[j + 4].y : v[j].y;
            }
            const bool h2b = (k8 >> 1) & 1;
#pragma unroll
            for (int j = 0; j < 2; j++) {
                float sx = h2b ? w[j].x : w[j + 2].x;
                float sy = h2b ? w[j].y : w[j + 2].y;
                float rx = __shfl_xor_sync(0xffffffffu, sx, 2);
                float ry = __shfl_xor_sync(0xffffffffu, sy, 2);
                if (h2b) { w[j + 2].x += rx; w[j + 2].y += ry; }
                else     { w[j].x     += rx; w[j].y     += ry; }
            }
            float2 u0, u1;
            u0.x = h2b ? w[2].x : w[0].x;  u0.y = h2b ? w[2].y : w[0].y;
            u1.x = h2b ? w[3].x : w[1].x;  u1.y = h2b ? w[3].y : w[1].y;
            const bool h1b = k8 & 1;
            {
                float sx = h1b ? u0.x : u1.x;
                float sy = h1b ? u0.y : u1.y;
                float rx = __shfl_xor_sync(0xffffffffu, sx, 1);
                float ry = __shfl_xor_sync(0xffffffffu, sy, 1);
                if (h1b) { u1.x += rx; u1.y += ry; }
                else     { u0.x += rx; u0.y += ry; }
            }
            float2 fin;
            fin.x = h1b ? u1.x : u0.x;
            fin.y = h1b ? u1.y : u0.y;
            st_remote_f2(inr_b + send_off, dst, fin);
        }
        __syncwarp();
        if (lane == 0) mbar_arrive_remote(mbr, dst);

        // ================= segment B: z matvec (hides r flight) =================
#pragma unroll
        for (int j = 0; j < 8; j++) v[j] = make_float2(0.f, 0.f);
#pragma unroll
        for (int kk = 0; kk < 8; kk++) {
            float4 u  = UzR[kk];
            float4 h4 = *reinterpret_cast<const float4*>(&sm[hb + kk * 4]);
            float2 u01 = make_float2(u.x, u.y), u23 = make_float2(u.z, u.w);
            const float hv[4] = {h4.x, h4.y, h4.z, h4.w};
#pragma unroll
            for (int b = 0; b < 4; b++) {
                float2 h2 = make_float2(hv[b], hv[b]);
                v[2 * b]     = ffma2(u01, h2, v[2 * b]);
                v[2 * b + 1] = ffma2(u23, h2, v[2 * b + 1]);
            }
        }
        {
            const bool h4b = (k8 >> 2) & 1;
#pragma unroll
            for (int j = 0; j < 4; j++) {
                float sx = h4b ? v[j].x : v[j + 4].x;
                float sy = h4b ? v[j].y : v[j + 4].y;
                float rx = __shfl_xor_sync(0xffffffffu, sx, 4);
                float ry = __shfl_xor_sync(0xffffffffu, sy, 4);
                if (h4b) { v[j + 4].x += rx; v[j + 4].y += ry; }
                else     { v[j].x     += rx; v[j].y     += ry; }
            }
            float2 w[4];
#pragma unroll
            for (int j = 0; j < 4; j++) {
                w[j].x = h4b ? v[j + 4].x : v[j].x;
                w[j].y = h4b ? v[j + 4].y : v[j].y;
            }
            const bool h2b = (k8 >> 1) & 1;
#pragma unroll
            for (int j = 0; j < 2; j++) {
                float sx = h2b ? w[j].x : w[j + 2].x;
                float sy = h2b ? w[j].y : w[j + 2].y;
                float rx = __shfl_xor_sync(0xffffffffu, sx, 2);
                float ry = __shfl_xor_sync(0xffffffffu, sy, 2);
                if (h2b) { w[j + 2].x += rx; w[j + 2].y += ry; }
                else     { w[j].x     += rx; w[j].y     += ry; }
            }
            float2 u0, u1;
            u0.x = h2b ? w[2].x : w[0].x;  u0.y = h2b ? w[2].y : w[0].y;
            u1.x = h2b ? w[3].x : w[1].x;  u1.y = h2b ? w[3].y : w[1].y;
            const bool h1b = k8 & 1;
            {
                float sx = h1b ? u0.x : u1.x;
                float sy = h1b ? u0.y : u1.y;
                float rx = __shfl_xor_sync(0xffffffffu, sx, 1);
                float ry = __shfl_xor_sync(0xffffffffu, sy, 1);
                if (h1b) { u1.x += rx; u1.y += ry; }
                else     { u0.x += rx; u0.y += ry; }
            }
            float2 fin;
            fin.x = h1b ? u1.x : u0.x;
            fin.y = h1b ? u1.y : u0.y;
            st_remote_f2(inz_b + ph * 4096u + send_off, dst, fin);
        }
        __syncwarp();
        if (lane == 0) mbar_arrive_remote(mbz, dst);

        // ================= segment C: r reduce + r*h publish =================
        if (tid < 256) {
            mbar_wait_parity(mbr, ph);   // fast path: flight hidden by segment B
            float sr = xrv;
#pragma unroll
            for (int s = 0; s < 4; s++)
                sr += sm[INR_OFF + (s * 4 + rb) * 64 + rcl];
            const float r = hsig(sr);
            sm[RHT_OFF + rswz + rb] = r * sm[HT_OFF + rswz + rb];
        }
        __syncthreads();

        // ================= segment D: candidate matvec (hides z flight) =======
#pragma unroll
        for (int j = 0; j < 8; j++) v[j] = make_float2(0.f, 0.f);
#pragma unroll
        for (int kk = 0; kk < 8; kk++) {
            const int krow = (k8 * 8 + kk) * 256 + crot;
            float4 u  = *reinterpret_cast<const float4*>(&sm[UH_OFF + krow]);
            float4 r4 = *reinterpret_cast<const float4*>(&sm[rhb + kk * 4]);
            float2 u01 = make_float2(u.x, u.y), u23 = make_float2(u.z, u.w);
            const float rv[4] = {r4.x, r4.y, r4.z, r4.w};
#pragma unroll
            for (int b = 0; b < 4; b++) {
                float2 r2 = make_float2(rv[b], rv[b]);
                v[2 * b]     = ffma2(u01, r2, v[2 * b]);
                v[2 * b + 1] = ffma2(u23, r2, v[2 * b + 1]);
            }
        }
        {
            const bool h4b = (k8 >> 2) & 1;
#pragma unroll
            for (int j = 0; j < 4; j++) {
                float sx = h4b ? v[j].x : v[j + 4].x;
                float sy = h4b ? v[j].y : v[j + 4].y;
                float rx = __shfl_xor_sync(0xffffffffu, sx, 4);
                float ry = __shfl_xor_sync(0xffffffffu, sy, 4);
                if (h4b) { v[j + 4].x += rx; v[j + 4].y += ry; }
                else     { v[j].x     += rx; v[j].y     += ry; }
            }
            float2 w[4];
#pragma unroll
            for (int j = 0; j < 4; j++) {
                w[j].x = h4b ? v[j + 4].x : v[j].x;
                w[j].y = h4b ? v[j + 4].y : v[j].y;
            }
            const bool h2b = (k8 >> 1) & 1;
#pragma unroll
            for (int j = 0; j < 2; j++) {
                float sx = h2b ? w[j].x : w[j + 2].x;
                float sy = h2b ? w[j].y : w[j + 2].y;
                float rx = __shfl_xor_sync(0xffffffffu, sx, 2);
                float ry = __shfl_xor_sync(0xffffffffu, sy, 2);
                if (h2b) { w[j + 2].x += rx; w[j + 2].y += ry; }
                else     { w[j].x     += rx; w[j].y     += ry; }
            }
            float2 u0, u1;
            u0.x = h2b ? w[2].x : w[0].x;  u0.y = h2b ? w[2].y : w[0].y;
            u1.x = h2b ? w[3].x : w[1].x;  u1.y = h2b ? w[3].y : w[1].y;
            const bool h1b = k8 & 1;
            {
                float sx = h1b ? u0.x : u1.x;
                float sy = h1b ? u0.y : u1.y;
                float rx = __shfl_xor_sync(0xffffffffu, sx, 1);
                float ry = __shfl_xor_sync(0xffffffffu, sy, 1);
                if (h1b) { u1.x += rx; u1.y += ry; }
                else     { u0.x += rx; u0.y += ry; }
            }
            float2 fin;
            fin.x = h1b ? u1.x : u0.x;
            fin.y = h1b ? u1.y : u0.y;
            st_remote_f2(inh_b + send_off, dst, fin);
        }
        __syncwarp();
        if (lane == 0) mbar_arrive_remote(mbh, dst);

        // ================= segments E/F: z reduce, h update =================
        if (tid < 256) {
            mbar_wait_parity(mbz, ph);   // fast path: flight hidden by C + D
            float sz = xzv;
#pragma unroll
            for (int s = 0; s < 4; s++)
                sz += sm[INZ_OFF + (int)ph * 1024 + (s * 4 + rb) * 64 + rcl];
            const float zk = hsig(sz);

            mbar_wait_parity(mbh, ph);   // partially hidden by z reduce
            float sh = xhv;
#pragma unroll
            for (int s = 0; s < 4; s++)
                sh += sm[INH_OFF + (s * 4 + rb) * 64 + rcl];
            const float hh = tanhf(sh);
            h_reg = zk * h_reg + (1.0f - zk) * hh;
            sm[HT_OFF + rswz + rb] = h_reg;
        }
        __syncthreads();
    }

    if (tid < 256)
        out[(size_t)bglob * Hh + cglob] = h_reg;

    cluster_sync_();
}

extern "C" void kernel_launch(void* const* d_in, const int* in_sizes, int n_in,
                              void* d_out, int out_size) {
    (void)in_sizes; (void)n_in; (void)out_size;
    const float* x  = (const float*)d_in[0];
    const float* Wz = (const float*)d_in[1];
    const float* Wr = (const float*)d_in[2];
    const float* Wh = (const float*)d_in[3];
    const float* Uz = (const float*)d_in[4];
    const float* Ur = (const float*)d_in[5];
    const float* Uh = (const float*)d_in[6];
    const float* bz = (const float*)d_in[7];
    const float* br = (const float*)d_in[8];
    const float* bh = (const float*)d_in[9];
    float* out = (float*)d_out;

    static int smem_set = 0;
    if (!smem_set) {
        cudaFuncSetAttribute(scan_cluster_kernel,
                             cudaFuncAttributeMaxDynamicSharedMemorySize,
                             SMEM_FLOATS * sizeof(float));
        cudaFuncSetAttribute(proj_mma_kernel,
                             cudaFuncAttributeMaxDynamicSharedMemorySize,
                             PROJ_SMEM_BYTES);
        smem_set = 1;
    }

    proj_mma_kernel<<<BT / 128, 256, PROJ_SMEM_BYTES>>>(x, Wz, Wr, Wh, bz, br, bh);
    scan_cluster_kernel<<<Bb, 512, SMEM_FLOATS * sizeof(float)>>>(Uz, Ur, Uh, out);
}

// round 14
// speedup vs baseline: 1.2505x; 1.2505x over previous
#include <cuda_runtime.h>
#include <cuda_bf16.h>
#include <cstdint>

#define Bb   128
#define Tt   1024
#define Dd   256
#define Hh   256
#define BT   (Bb * Tt)

__device__ float g_xz[(size_t)BT * Hh];
__device__ float g_xr[(size_t)BT * Hh];
__device__ float g_xh[(size_t)BT * Hh];

// Pre-converted, pre-transposed W: [gate][n][k] bf16 hi/lo.
__device__ __nv_bfloat16 g_wt_hi[3][Hh][Dd];
__device__ __nv_bfloat16 g_wt_lo[3][Hh][Dd];

__device__ __forceinline__ float2 ffma2(float2 a, float2 b, float2 c) {
    float2 d;
    asm("fma.rn.f32x2 %0, %1, %2, %3;"
        : "=l"(*reinterpret_cast<unsigned long long*>(&d))
        : "l"(*reinterpret_cast<const unsigned long long*>(&a)),
          "l"(*reinterpret_cast<const unsigned long long*>(&b)),
          "l"(*reinterpret_cast<const unsigned long long*>(&c)));
    return d;
}

__device__ __forceinline__ float hsig(float x) {
    return fminf(fmaxf(fmaf(x, 0.2f, 0.5f), 0.0f), 1.0f);
}

__device__ __forceinline__ uint32_t smem_u32(const void* p) {
    uint32_t a;
    asm("{ .reg .u64 t; cvta.to.shared.u64 t, %1; cvt.u32.u64 %0, t; }"
        : "=r"(a) : "l"(p));
    return a;
}

__device__ __forceinline__ void st_remote_f4(uint32_t laddr, int rank, float4 v) {
    uint32_t raddr;
    asm volatile("mapa.shared::cluster.u32 %0, %1, %2;"
                 : "=r"(raddr) : "r"(laddr), "r"(rank));
    asm volatile("st.shared::cluster.v4.f32 [%0], {%1, %2, %3, %4};"
                 :: "r"(raddr), "f"(v.x), "f"(v.y), "f"(v.z), "f"(v.w) : "memory");
}

__device__ __forceinline__ void st_remote_f2(uint32_t laddr, int rank, float2 v) {
    uint32_t raddr;
    asm volatile("mapa.shared::cluster.u32 %0, %1, %2;"
                 : "=r"(raddr) : "r"(laddr), "r"(rank));
    asm volatile("st.shared::cluster.v2.f32 [%0], {%1, %2};"
                 :: "r"(raddr), "f"(v.x), "f"(v.y) : "memory");
}

__device__ __forceinline__ void cluster_sync_() {
    asm volatile("barrier.cluster.arrive.aligned;" ::: "memory");
    asm volatile("barrier.cluster.wait.aligned;" ::: "memory");
}

__device__ __forceinline__ uint32_t ctarank_() {
    uint32_t r;
    asm("mov.u32 %0, %%cluster_ctarank;" : "=r"(r));
    return r;
}

__device__ __forceinline__ void mbar_arrive_remote(uint32_t laddr, int rank) {
    uint32_t raddr;
    asm volatile("mapa.shared::cluster.u32 %0, %1, %2;"
                 : "=r"(raddr) : "r"(laddr), "r"(rank));
    asm volatile("mbarrier.arrive.release.cluster.shared::cluster.b64 _, [%0];"
                 :: "r"(raddr) : "memory");
}

__device__ __forceinline__ void mbar_wait_parity(uint32_t addr, uint32_t parity) {
    asm volatile(
        "{\n\t"
        ".reg .pred P;\n\t"
        "WL_%=:\n\t"
        "mbarrier.try_wait.parity.acquire.cluster.shared::cta.b64 P, [%0], %1, 0x989680;\n\t"
        "@!P bra WL_%=;\n\t"
        "}"
        :: "r"(addr), "r"(parity) : "memory");
}

// ---------------------------------------------------------------------------
// One-shot W transpose + bf16 hi/lo split: g_wt_*[g][n][k] = split(W_g[k][n]).
// Grid (8, 8, 3), block (32, 32). Tiny (~10us).
// ---------------------------------------------------------------------------
__global__ void conv_w_kernel(const float* __restrict__ Wz,
                              const float* __restrict__ Wr,
                              const float* __restrict__ Wh)
{
    __shared__ float tile[32][33];
    const float* W = (blockIdx.z == 0) ? Wz : (blockIdx.z == 1) ? Wr : Wh;
    const int tx = threadIdx.x, ty = threadIdx.y;
    const int k0 = blockIdx.y * 32, n0 = blockIdx.x * 32;

    // coalesced read: W[k0+ty][n0+tx]
    tile[ty][tx] = W[(size_t)(k0 + ty) * Hh + n0 + tx];
    __syncthreads();

    // coalesced write: out[n0+ty][k0+tx] = tile[tx][ty]
    const float v = tile[tx][ty];
    const __nv_bfloat16 hi = __float2bfloat16(v);
    const __nv_bfloat16 lo = __float2bfloat16(v - __bfloat162float(hi));
    g_wt_hi[blockIdx.z][n0 + ty][k0 + tx] = hi;
    g_wt_lo[blockIdx.z][n0 + ty][k0 + tx] = lo;
}

// ---------------------------------------------------------------------------
// HMMA projection (R9 structure; B-fill is now a pure coalesced copy of
// pre-converted W — the per-chunk f32 load + split + scatter is gone).
// ---------------------------------------------------------------------------
#define RS     264
#define PA_HI  0
#define PA_LO  67584
#define PB_HI  135168
#define PB_LO  168960
#define PROJ_SMEM_BYTES 202752

__device__ __forceinline__ void ldsm_x4(uint32_t addr, uint32_t* r) {
    asm volatile("ldmatrix.sync.aligned.m8n8.x4.shared.b16 {%0,%1,%2,%3}, [%4];"
                 : "=r"(r[0]), "=r"(r[1]), "=r"(r[2]), "=r"(r[3]) : "r"(addr));
}
__device__ __forceinline__ void ldsm_x2(uint32_t addr, uint32_t* r) {
    asm volatile("ldmatrix.sync.aligned.m8n8.x2.shared.b16 {%0,%1}, [%2];"
                 : "=r"(r[0]), "=r"(r[1]) : "r"(addr));
}
__device__ __forceinline__ void mma_bf16(float* c, const uint32_t* a, const uint32_t* b) {
    asm volatile(
        "mma.sync.aligned.m16n8k16.row.col.f32.bf16.bf16.f32 "
        "{%0,%1,%2,%3}, {%4,%5,%6,%7}, {%8,%9}, {%0,%1,%2,%3};"
        : "+f"(c[0]), "+f"(c[1]), "+f"(c[2]), "+f"(c[3])
        : "r"(a[0]), "r"(a[1]), "r"(a[2]), "r"(a[3]), "r"(b[0]), "r"(b[1]));
}

__global__ __launch_bounds__(256, 1) void proj_mma_kernel(
    const float* __restrict__ x,
    const float* __restrict__ bz, const float* __restrict__ br,
    const float* __restrict__ bh)
{
    extern __shared__ char dsm[];
    const uint32_t sbase = smem_u32(dsm);

    const int tid  = threadIdx.x;
    const int wid  = tid >> 5;
    const int lane = tid & 31;
    const int row0 = blockIdx.x * 128;
    const int mg   = wid >> 1;
    const int ng   = wid & 1;

    // ---- convert x tile -> A_hi / A_lo (per-CTA unique; kept) ----
    for (int idx = tid; idx < 128 * 64; idx += 256) {
        int m = idx >> 6, kq = (idx & 63) << 2;
        float4 v = *reinterpret_cast<const float4*>(&x[(size_t)(row0 + m) * Dd + kq]);
        __nv_bfloat16 h0 = __float2bfloat16(v.x), h1 = __float2bfloat16(v.y);
        __nv_bfloat16 h2 = __float2bfloat16(v.z), h3 = __float2bfloat16(v.w);
        __nv_bfloat16 l0 = __float2bfloat16(v.x - __bfloat162float(h0));
        __nv_bfloat16 l1 = __float2bfloat16(v.y - __bfloat162float(h1));
        __nv_bfloat16 l2 = __float2bfloat16(v.z - __bfloat162float(h2));
        __nv_bfloat16 l3 = __float2bfloat16(v.w - __bfloat162float(h3));
        uint32_t off = (uint32_t)(m * RS + kq) * 2u;
        *reinterpret_cast<__nv_bfloat162*>(dsm + PA_HI + off)     = __halves2bfloat162(h0, h1);
        *reinterpret_cast<__nv_bfloat162*>(dsm + PA_HI + off + 4) = __halves2bfloat162(h2, h3);
        *reinterpret_cast<__nv_bfloat162*>(dsm + PA_LO + off)     = __halves2bfloat162(l0, l1);
        *reinterpret_cast<__nv_bfloat162*>(dsm + PA_LO + off + 4) = __halves2bfloat162(l2, l3);
    }

    const int arow = 32 * mg + (lane & 15);
    const int ako  = (lane >> 4) * 8;
    const uint32_t ah0 = sbase + PA_HI + (uint32_t)(arow * RS + ako) * 2u;
    const uint32_t ah1 = ah0 + (uint32_t)(16 * RS) * 2u;
    const uint32_t al0 = sbase + PA_LO + (uint32_t)(arow * RS + ako) * 2u;
    const uint32_t al1 = al0 + (uint32_t)(16 * RS) * 2u;

    const int nrow = 32 * ng + (lane & 7);
    const int bko  = (lane & 8) ? 8 : 0;
    const uint32_t bph = sbase + PB_HI + (uint32_t)(nrow * RS + bko) * 2u;
    const uint32_t bpl = sbase + PB_LO + (uint32_t)(nrow * RS + bko) * 2u;

    const int gid = lane >> 2;
    const int tig = lane & 3;

    // B-copy indexing: 64 rows x 512B = 2048 uint4; 8 per thread.
    const int brow = tid >> 2;            // 0..63 (row), 4 threads per row
    const int bu4  = (tid & 3) * 8;       // starting uint4 within row (of 32)

    for (int g = 0; g < 3; g++) {
        const float* bs = (g == 0) ? bz : (g == 1) ? br : bh;
        float* outp     = (g == 0) ? g_xz : (g == 1) ? g_xr : g_xh;

        for (int nc = 0; nc < 4; nc++) {
            const int n0 = nc * 64;
            __syncthreads();   // prior chunk's ldmatrix reads complete

            // ---- B chunk: pure coalesced copy of pre-converted bf16 W ----
            {
                const uint4* srch = reinterpret_cast<const uint4*>(
                    &g_wt_hi[g][n0 + brow][0]);
                const uint4* srcl = reinterpret_cast<const uint4*>(
                    &g_wt_lo[g][n0 + brow][0]);
                uint4* dsth = reinterpret_cast<uint4*>(dsm + PB_HI + brow * RS * 2);
                uint4* dstl = reinterpret_cast<uint4*>(dsm + PB_LO + brow * RS * 2);
#pragma unroll
                for (int u = 0; u < 8; u++) {
                    dsth[bu4 + u] = srch[bu4 + u];
                    dstl[bu4 + u] = srcl[bu4 + u];
                }
            }
            __syncthreads();

            // ---- MMA mainloop (m32n32 per warp) ----
            float acc[2][4][4];
#pragma unroll
            for (int mt = 0; mt < 2; mt++)
#pragma unroll
                for (int nt = 0; nt < 4; nt++)
#pragma unroll
                    for (int j = 0; j < 4; j++) acc[mt][nt][j] = 0.0f;

#pragma unroll 4
            for (int ks = 0; ks < 16; ks++) {
                const uint32_t ko = (uint32_t)ks * 32u;
                uint32_t afh[2][4], afl[2][4];
                ldsm_x4(ah0 + ko, afh[0]);
                ldsm_x4(ah1 + ko, afh[1]);
                ldsm_x4(al0 + ko, afl[0]);
                ldsm_x4(al1 + ko, afl[1]);
#pragma unroll
                for (int nt = 0; nt < 4; nt++) {
                    const uint32_t boff = (uint32_t)(nt * 8 * RS) * 2u + ko;
                    uint32_t bfh[2], bfl[2];
                    ldsm_x2(bph + boff, bfh);
                    ldsm_x2(bpl + boff, bfl);
#pragma unroll
                    for (int mt = 0; mt < 2; mt++) {
                        mma_bf16(acc[mt][nt], afh[mt], bfh);
                        mma_bf16(acc[mt][nt], afh[mt], bfl);
                        mma_bf16(acc[mt][nt], afl[mt], bfh);
                    }
                }
            }

            // ---- epilogue: bias + direct STG ----
#pragma unroll
            for (int mt = 0; mt < 2; mt++) {
                const int row = row0 + 32 * mg + 16 * mt + gid;
#pragma unroll
                for (int nt = 0; nt < 4; nt++) {
                    const int col = n0 + 32 * ng + 8 * nt + tig * 2;
                    float2 bv = *reinterpret_cast<const float2*>(&bs[col]);
                    float2 v0 = make_float2(acc[mt][nt][0] + bv.x, acc[mt][nt][1] + bv.y);
                    float2 v1 = make_float2(acc[mt][nt][2] + bv.x, acc[mt][nt][3] + bv.y);
                    *reinterpret_cast<float2*>(&outp[(size_t)row * Hh + col])       = v0;
                    *reinterpret_cast<float2*>(&outp[(size_t)(row + 8) * Hh + col]) = v1;
                }
            }
        }
    }
}

// ---------------------------------------------------------------------------
// Cluster scan (identical to R11 — best, validated; 3.067ms)
// ---------------------------------------------------------------------------
#define UH_OFF   0
#define HT_OFF   16384
#define RHT_OFF  (HT_OFF + 288)
#define INZR_OFF (RHT_OFF + 288)
#define INH_OFF  (INZR_OFF + 2048)
#define MBAR_OFF (INH_OFF + 1024)
#define SMEM_FLOATS (MBAR_OFF + 4)

__global__ void __cluster_dims__(4, 1, 1) __launch_bounds__(512, 1)
scan_cluster_kernel(const float* __restrict__ Uz, const float* __restrict__ Ur,
                    const float* __restrict__ Uh, float* __restrict__ out)
{
    extern __shared__ float sm[];
    const int tid  = threadIdx.x;
    const int rank = (int)ctarank_();
    const int cluster_id = blockIdx.x >> 2;

    const uint32_t mbzr = smem_u32(&sm[MBAR_OFF]);
    const uint32_t mbh  = smem_u32(&sm[MBAR_OFF + 2]);

    for (int i = tid; i < 64 * 64; i += 512) {
        int k = i >> 6, c = (i & 63) * 4;
        int cs = (c + ((k >> 3) & 7) * 4) & 255;
        *reinterpret_cast<float4*>(&sm[UH_OFF + k * 256 + cs]) =
            *reinterpret_cast<const float4*>(&Uh[(size_t)(64 * rank + k) * Hh + c]);
    }
    if (tid < 256) {
        int k = tid >> 2, b = tid & 3;
        sm[HT_OFF + k * 4 + ((k >> 4) & 3) * 8 + b] = 0.0f;
    }
    if (tid == 0) {
        asm volatile("mbarrier.init.shared.b64 [%0], %1;" :: "r"(mbzr), "r"(16) : "memory");
        asm volatile("mbarrier.init.shared.b64 [%0], %1;" :: "r"(mbh),  "r"(16) : "memory");
    }

    const int gate = tid >> 8;
    const int p1cg = (tid & 255) >> 2;
    const int p1k  = tid & 3;
    const int p1c0 = p1cg * 4;
    const int p1dst = p1cg >> 4;
    const int p1cl  = (p1cg & 15) * 4;
    const int p1hb  = HT_OFF + p1k * 72;

    float4 Ug[16];
    {
        const float* Usrc = gate ? Ur : Uz;
#pragma unroll
        for (int kk = 0; kk < 16; kk++)
            Ug[kk] = *reinterpret_cast<const float4*>(
                &Usrc[(size_t)(64 * rank + p1k * 16 + kk) * Hh + p1c0]);
    }

    const int p2cg = tid >> 3;
    const int p2k  = tid & 7;
    const int p2crot = (p2cg * 4 + p2k * 4) & 255;
    const int p2dst  = p2cg >> 4;
    const int p2cl   = (p2cg & 15) * 4;
    const int p2hb   = RHT_OFF + 32 * p2k + 8 * (p2k >> 1);

    const int rtid  = tid & 255;
    const int rb    = rtid >> 6;
    const int rcl   = rtid & 63;
    const int rswz  = rcl * 4 + ((rcl >> 4) & 3) * 8;
    const int cglob = rank * 64 + rcl;
    const int bglob = cluster_id * 4 + rb;
    const size_t xbase = ((size_t)bglob * Tt) * Hh + cglob;

    const uint32_t inzr_base = smem_u32(&sm[INZR_OFF]);
    const uint32_t inh_base  = smem_u32(&sm[INH_OFF]);

    float h_reg = 0.0f, zkeep = 0.0f;

    float xz_c = 0.f, xr_c = 0.f, xh_c = 0.f;
    if (tid < 256) { xz_c = g_xz[xbase]; xh_c = g_xh[xbase]; }
    else           { xr_c = g_xr[xbase]; }

    __syncthreads();
    cluster_sync_();

#pragma unroll 1
    for (int t = 0; t < Tt; t++) {
        const uint32_t ph = (uint32_t)(t & 1);

        float xz_n = 0.f, xr_n = 0.f, xh_n = 0.f;
        {
            const int tn = (t + 1 < Tt) ? (t + 1) : t;
            const size_t xoff = xbase + (size_t)tn * Hh;
            if (tid < 256) { xz_n = g_xz[xoff]; xh_n = g_xh[xoff]; }
            else           { xr_n = g_xr[xoff]; }
        }
        const float xzv = xz_c, xrv = xr_c, xhv = xh_c;

        float2 v[8];
#pragma unroll
        for (int j = 0; j < 8; j++) v[j] = make_float2(0.f, 0.f);
#pragma unroll
        for (int kk = 0; kk < 16; kk++) {
            float4 h4 = *reinterpret_cast<const float4*>(&sm[p1hb + kk * 4]);
            float2 u01 = make_float2(Ug[kk].x, Ug[kk].y);
            float2 u23 = make_float2(Ug[kk].z, Ug[kk].w);
            const float hb[4] = {h4.x, h4.y, h4.z, h4.w};
#pragma unroll
            for (int b = 0; b < 4; b++) {
                float2 h2 = make_float2(hb[b], hb[b]);
                v[2 * b]     = ffma2(u01, h2, v[2 * b]);
                v[2 * b + 1] = ffma2(u23, h2, v[2 * b + 1]);
            }
        }
        {
            const bool hi2 = (p1k >> 1) & 1;
#pragma unroll
            for (int j = 0; j < 4; j++) {
                float sx = hi2 ? v[j].x : v[j + 4].x;
                float sy = hi2 ? v[j].y : v[j + 4].y;
                float rx = __shfl_xor_sync(0xffffffffu, sx, 2);
                float ry = __shfl_xor_sync(0xffffffffu, sy, 2);
                if (hi2) { v[j + 4].x += rx; v[j + 4].y += ry; }
                else     { v[j].x     += rx; v[j].y     += ry; }
            }
            float2 w[4];
#pragma unroll
            for (int j = 0; j < 4; j++) {
                w[j].x = hi2 ? v[j + 4].x : v[j].x;
                w[j].y = hi2 ? v[j + 4].y : v[j].y;
            }
            const bool hi1 = p1k & 1;
#pragma unroll
            for (int j = 0; j < 2; j++) {
                float sx = hi1 ? w[j].x : w[j + 2].x;
                float sy = hi1 ? w[j].y : w[j + 2].y;
                float rx = __shfl_xor_sync(0xffffffffu, sx, 1);
                float ry = __shfl_xor_sync(0xffffffffu, sy, 1);
                if (hi1) { w[j + 2].x += rx; w[j + 2].y += ry; }
                else     { w[j].x     += rx; w[j].y     += ry; }
            }
            float2 f0, f1;
            f0.x = hi1 ? w[2].x : w[0].x;  f0.y = hi1 ? w[2].y : w[0].y;
            f1.x = hi1 ? w[3].x : w[1].x;  f1.y = hi1 ? w[3].y : w[1].y;
            uint32_t addr = inzr_base +
                (uint32_t)((((rank * 2 + gate) * 4 + p1k) * 64 + p1cl) * 4);
            st_remote_f4(addr, p1dst, make_float4(f0.x, f0.y, f1.x, f1.y));
        }
        __syncwarp();
        if ((tid & 31) == 0) mbar_arrive_remote(mbzr, p1dst);

        mbar_wait_parity(mbzr, ph);
        if (tid < 256) {
            float sz = xzv;
#pragma unroll
            for (int s = 0; s < 4; s++)
                sz += sm[INZR_OFF + ((s * 2 + 0) * 4 + rb) * 64 + rcl];
            zkeep = hsig(sz);
        } else {
            float sr = xrv;
#pragma unroll
            for (int s = 0; s < 4; s++)
                sr += sm[INZR_OFF + ((s * 2 + 1) * 4 + rb) * 64 + rcl];
            const float r = hsig(sr);
            const float hprev = sm[HT_OFF + rswz + rb];
            sm[RHT_OFF + rswz + rb] = r * hprev;
        }
        __syncthreads();

#pragma unroll
        for (int j = 0; j < 8; j++) v[j] = make_float2(0.f, 0.f);
#pragma unroll
        for (int kk = 0; kk < 8; kk++) {
            const int krow = (p2k * 8 + kk) * 256 + p2crot;
            float4 uh = *reinterpret_cast<const float4*>(&sm[UH_OFF + krow]);
            float4 r4 = *reinterpret_cast<const float4*>(&sm[p2hb + kk * 4]);
            float2 u01 = make_float2(uh.x, uh.y);
            float2 u23 = make_float2(uh.z, uh.w);
            const float rv[4] = {r4.x, r4.y, r4.z, r4.w};
#pragma unroll
            for (int b = 0; b < 4; b++) {
                float2 r2 = make_float2(rv[b], rv[b]);
                v[2 * b]     = ffma2(u01, r2, v[2 * b]);
                v[2 * b + 1] = ffma2(u23, r2, v[2 * b + 1]);
            }
        }
        {
            const bool h4b = (p2k >> 2) & 1;
#pragma unroll
            for (int j = 0; j < 4; j++) {
                float sx = h4b ? v[j].x : v[j + 4].x;
                float sy = h4b ? v[j].y : v[j + 4].y;
                float rx = __shfl_xor_sync(0xffffffffu, sx, 4);
                float ry = __shfl_xor_sync(0xffffffffu, sy, 4);
                if (h4b) { v[j + 4].x += rx; v[j + 4].y += ry; }
                else     { v[j].x     += rx; v[j].y     += ry; }
            }
            float2 w[4];
#pragma unroll
            for (int j = 0; j < 4; j++) {
                w[j].x = h4b ? v[j + 4].x : v[j].x;
                w[j].y = h4b ? v[j + 4].y : v[j].y;
            }
            const bool h2b = (p2k >> 1) & 1;
#pragma unroll
            for (int j = 0; j < 2; j++) {
                float sx = h2b ? w[j].x : w[j + 2].x;
                float sy = h2b ? w[j].y : w[j + 2].y;
                float rx = __shfl_xor_sync(0xffffffffu, sx, 2);
                float ry = __shfl_xor_sync(0xffffffffu, sy, 2);
                if (h2b) { w[j + 2].x += rx; w[j + 2].y += ry; }
                else     { w[j].x     += rx; w[j].y     += ry; }
            }
            float2 u0, u1;
            u0.x = h2b ? w[2].x : w[0].x;  u0.y = h2b ? w[2].y : w[0].y;
            u1.x = h2b ? w[3].x : w[1].x;  u1.y = h2b ? w[3].y : w[1].y;
            const bool h1b = p2k & 1;
            {
                float sx = h1b ? u0.x : u1.x;
                float sy = h1b ? u0.y : u1.y;
                float rx = __shfl_xor_sync(0xffffffffu, sx, 1);
                float ry = __shfl_xor_sync(0xffffffffu, sy, 1);
                if (h1b) { u1.x += rx; u1.y += ry; }
                else     { u0.x += rx; u0.y += ry; }
            }
            float2 fin;
            fin.x = h1b ? u1.x : u0.x;
            fin.y = h1b ? u1.y : u0.y;
            uint32_t addr = inh_base +
                (uint32_t)(((rank * 4 + (p2k >> 1)) * 64 + p2cl + (p2k & 1) * 2) * 4);
            st_remote_f2(addr, p2dst, fin);
        }
        __syncwarp();
        if ((tid & 31) == 0) mbar_arrive_remote(mbh, p2dst);

        if (tid < 256) {
            mbar_wait_parity(mbh, ph);
            float sh = xhv;
#pragma unroll
            for (int s = 0; s < 4; s++)
                sh += sm[INH_OFF + (s * 4 + rb) * 64 + rcl];
            const float hh = tanhf(sh);
            h_reg = zkeep * h_reg + (1.0f - zkeep) * hh;
            sm[HT_OFF + rswz + rb] = h_reg;
        }
        __syncthreads();

        xz_c = xz_n; xr_c = xr_n; xh_c = xh_n;
    }

    if (tid < 256)
        out[(size_t)bglob * Hh + cglob] = h_reg;

    cluster_sync_();
}

extern "C" void kernel_launch(void* const* d_in, const int* in_sizes, int n_in,
                              void* d_out, int out_size) {
    (void)in_sizes; (void)n_in; (void)out_size;
    const float* x  = (const float*)d_in[0];
    const float* Wz = (const float*)d_in[1];
    const float* Wr = (const float*)d_in[2];
    const float* Wh = (const float*)d_in[3];
    const float* Uz = (const float*)d_in[4];
    const float* Ur = (const float*)d_in[5];
    const float* Uh = (const float*)d_in[6];
    const float* bz = (const float*)d_in[7];
    const float* br = (const float*)d_in[8];
    const float* bh = (const float*)d_in[9];
    float* out = (float*)d_out;

    static int smem_set = 0;
    if (!smem_set) {
        cudaFuncSetAttribute(scan_cluster_kernel,
                             cudaFuncAttributeMaxDynamicSharedMemorySize,
                             SMEM_FLOATS * sizeof(float));
        cudaFuncSetAttribute(proj_mma_kernel,
                             cudaFuncAttributeMaxDynamicSharedMemorySize,
                             PROJ_SMEM_BYTES);
        smem_set = 1;
    }

    conv_w_kernel<<<dim3(8, 8, 3), dim3(32, 32)>>>(Wz, Wr, Wh);
    proj_mma_kernel<<<BT / 128, 256, PROJ_SMEM_BYTES>>>(x, bz, br, bh);
    scan_cluster_kernel<<<Bb, 512, SMEM_FLOATS * sizeof(float)>>>(Uz, Ur, Uh, out);
}

// round 15
// speedup vs baseline: 1.2685x; 1.0144x over previous
#include <cuda_runtime.h>
#include <cuda_bf16.h>
#include <cstdint>

#define Bb   128
#define Tt   1024
#define Dd   256
#define Hh   256
#define BT   (Bb * Tt)

__device__ float g_xz[(size_t)BT * Hh];
__device__ float g_xr[(size_t)BT * Hh];
__device__ float g_xh[(size_t)BT * Hh];

__device__ __forceinline__ float2 ffma2(float2 a, float2 b, float2 c) {
    float2 d;
    asm("fma.rn.f32x2 %0, %1, %2, %3;"
        : "=l"(*reinterpret_cast<unsigned long long*>(&d))
        : "l"(*reinterpret_cast<const unsigned long long*>(&a)),
          "l"(*reinterpret_cast<const unsigned long long*>(&b)),
          "l"(*reinterpret_cast<const unsigned long long*>(&c)));
    return d;
}

__device__ __forceinline__ float hsig(float x) {
    return fminf(fmaxf(fmaf(x, 0.2f, 0.5f), 0.0f), 1.0f);
}

// Branch-free tanh via MUFU: tanh(x) = 1 - 2/(e^{2x}+1).
// __expf -> ex2.approx, __fdividef -> rcp.approx+mul; saturates correctly
// (x>>0: e=inf -> 1; x<<0: e=0 -> -1). Rel err ~2^-20, far under budget.
__device__ __forceinline__ float fast_tanh(float x) {
    const float e = __expf(2.0f * x);
    return 1.0f - __fdividef(2.0f, e + 1.0f);
}

__device__ __forceinline__ uint32_t smem_u32(const void* p) {
    uint32_t a;
    asm("{ .reg .u64 t; cvta.to.shared.u64 t, %1; cvt.u32.u64 %0, t; }"
        : "=r"(a) : "l"(p));
    return a;
}

__device__ __forceinline__ void st_remote_f4(uint32_t laddr, int rank, float4 v) {
    uint32_t raddr;
    asm volatile("mapa.shared::cluster.u32 %0, %1, %2;"
                 : "=r"(raddr) : "r"(laddr), "r"(rank));
    asm volatile("st.shared::cluster.v4.f32 [%0], {%1, %2, %3, %4};"
                 :: "r"(raddr), "f"(v.x), "f"(v.y), "f"(v.z), "f"(v.w) : "memory");
}

__device__ __forceinline__ void st_remote_f2(uint32_t laddr, int rank, float2 v) {
    uint32_t raddr;
    asm volatile("mapa.shared::cluster.u32 %0, %1, %2;"
                 : "=r"(raddr) : "r"(laddr), "r"(rank));
    asm volatile("st.shared::cluster.v2.f32 [%0], {%1, %2};"
                 :: "r"(raddr), "f"(v.x), "f"(v.y) : "memory");
}

__device__ __forceinline__ void cluster_sync_() {
    asm volatile("barrier.cluster.arrive.aligned;" ::: "memory");
    asm volatile("barrier.cluster.wait.aligned;" ::: "memory");
}

__device__ __forceinline__ uint32_t ctarank_() {
    uint32_t r;
    asm("mov.u32 %0, %%cluster_ctarank;" : "=r"(r));
    return r;
}

__device__ __forceinline__ void mbar_arrive_remote(uint32_t laddr, int rank) {
    uint32_t raddr;
    asm volatile("mapa.shared::cluster.u32 %0, %1, %2;"
                 : "=r"(raddr) : "r"(laddr), "r"(rank));
    asm volatile("mbarrier.arrive.release.cluster.shared::cluster.b64 _, [%0];"
                 :: "r"(raddr) : "memory");
}

__device__ __forceinline__ void mbar_wait_parity(uint32_t addr, uint32_t parity) {
    asm volatile(
        "{\n\t"
        ".reg .pred P;\n\t"
        "WL_%=:\n\t"
        "mbarrier.try_wait.parity.acquire.cluster.shared::cta.b64 P, [%0], %1, 0x989680;\n\t"
        "@!P bra WL_%=;\n\t"
        "}"
        :: "r"(addr), "r"(parity) : "memory");
}

// ---------------------------------------------------------------------------
// HMMA projection (R9 version — proven best at ~692us)
// ---------------------------------------------------------------------------
#define RS     264
#define PA_HI  0
#define PA_LO  67584
#define PB_HI  135168
#define PB_LO  168960
#define PROJ_SMEM_BYTES 202752

__device__ __forceinline__ void ldsm_x4(uint32_t addr, uint32_t* r) {
    asm volatile("ldmatrix.sync.aligned.m8n8.x4.shared.b16 {%0,%1,%2,%3}, [%4];"
                 : "=r"(r[0]), "=r"(r[1]), "=r"(r[2]), "=r"(r[3]) : "r"(addr));
}
__device__ __forceinline__ void ldsm_x2(uint32_t addr, uint32_t* r) {
    asm volatile("ldmatrix.sync.aligned.m8n8.x2.shared.b16 {%0,%1}, [%2];"
                 : "=r"(r[0]), "=r"(r[1]) : "r"(addr));
}
__device__ __forceinline__ void mma_bf16(float* c, const uint32_t* a, const uint32_t* b) {
    asm volatile(
        "mma.sync.aligned.m16n8k16.row.col.f32.bf16.bf16.f32 "
        "{%0,%1,%2,%3}, {%4,%5,%6,%7}, {%8,%9}, {%0,%1,%2,%3};"
        : "+f"(c[0]), "+f"(c[1]), "+f"(c[2]), "+f"(c[3])
        : "r"(a[0]), "r"(a[1]), "r"(a[2]), "r"(a[3]), "r"(b[0]), "r"(b[1]));
}

__global__ __launch_bounds__(256, 1) void proj_mma_kernel(
    const float* __restrict__ x,
    const float* __restrict__ Wz, const float* __restrict__ Wr,
    const float* __restrict__ Wh,
    const float* __restrict__ bz, const float* __restrict__ br,
    const float* __restrict__ bh)
{
    extern __shared__ char dsm[];
    const uint32_t sbase = smem_u32(dsm);

    const int tid  = threadIdx.x;
    const int wid  = tid >> 5;
    const int lane = tid & 31;
    const int row0 = blockIdx.x * 128;
    const int mg   = wid >> 1;
    const int ng   = wid & 1;

    for (int idx = tid; idx < 128 * 64; idx += 256) {
        int m = idx >> 6, kq = (idx & 63) << 2;
        float4 v = *reinterpret_cast<const float4*>(&x[(size_t)(row0 + m) * Dd + kq]);
        __nv_bfloat16 h0 = __float2bfloat16(v.x), h1 = __float2bfloat16(v.y);
        __nv_bfloat16 h2 = __float2bfloat16(v.z), h3 = __float2bfloat16(v.w);
        __nv_bfloat16 l0 = __float2bfloat16(v.x - __bfloat162float(h0));
        __nv_bfloat16 l1 = __float2bfloat16(v.y - __bfloat162float(h1));
        __nv_bfloat16 l2 = __float2bfloat16(v.z - __bfloat162float(h2));
        __nv_bfloat16 l3 = __float2bfloat16(v.w - __bfloat162float(h3));
        uint32_t off = (uint32_t)(m * RS + kq) * 2u;
        *reinterpret_cast<__nv_bfloat162*>(dsm + PA_HI + off)     = __halves2bfloat162(h0, h1);
        *reinterpret_cast<__nv_bfloat162*>(dsm + PA_HI + off + 4) = __halves2bfloat162(h2, h3);
        *reinterpret_cast<__nv_bfloat162*>(dsm + PA_LO + off)     = __halves2bfloat162(l0, l1);
        *reinterpret_cast<__nv_bfloat162*>(dsm + PA_LO + off + 4) = __halves2bfloat162(l2, l3);
    }

    const int arow = 32 * mg + (lane & 15);
    const int ako  = (lane >> 4) * 8;
    const uint32_t ah0 = sbase + PA_HI + (uint32_t)(arow * RS + ako) * 2u;
    const uint32_t ah1 = ah0 + (uint32_t)(16 * RS) * 2u;
    const uint32_t al0 = sbase + PA_LO + (uint32_t)(arow * RS + ako) * 2u;
    const uint32_t al1 = al0 + (uint32_t)(16 * RS) * 2u;

    const int nrow = 32 * ng + (lane & 7);
    const int bko  = (lane & 8) ? 8 : 0;
    const uint32_t bph = sbase + PB_HI + (uint32_t)(nrow * RS + bko) * 2u;
    const uint32_t bpl = sbase + PB_LO + (uint32_t)(nrow * RS + bko) * 2u;

    const int gid = lane >> 2;
    const int tig = lane & 3;

    for (int g = 0; g < 3; g++) {
        const float* W  = (g == 0) ? Wz : (g == 1) ? Wr : Wh;
        const float* bs = (g == 0) ? bz : (g == 1) ? br : bh;
        float* outp     = (g == 0) ? g_xz : (g == 1) ? g_xr : g_xh;

        for (int nc = 0; nc < 4; nc++) {
            const int n0 = nc * 64;
            __syncthreads();

            for (int idx = tid; idx < 64 * 128; idx += 256) {
                int k2 = idx >> 6;
                int n  = idx & 63;
                float w0 = W[(size_t)(2 * k2) * Hh + n0 + n];
                float w1 = W[(size_t)(2 * k2 + 1) * Hh + n0 + n];
                __nv_bfloat16 h0 = __float2bfloat16(w0);
                __nv_bfloat16 h1 = __float2bfloat16(w1);
                __nv_bfloat16 l0 = __float2bfloat16(w0 - __bfloat162float(h0));
                __nv_bfloat16 l1 = __float2bfloat16(w1 - __bfloat162float(h1));
                uint32_t off = (uint32_t)(n * RS + 2 * k2) * 2u;
                *reinterpret_cast<__nv_bfloat162*>(dsm + PB_HI + off) = __halves2bfloat162(h0, h1);
                *reinterpret_cast<__nv_bfloat162*>(dsm + PB_LO + off) = __halves2bfloat162(l0, l1);
            }
            __syncthreads();

            float acc[2][4][4];
#pragma unroll
            for (int mt = 0; mt < 2; mt++)
#pragma unroll
                for (int nt = 0; nt < 4; nt++)
#pragma unroll
                    for (int j = 0; j < 4; j++) acc[mt][nt][j] = 0.0f;

#pragma unroll 4
            for (int ks = 0; ks < 16; ks++) {
                const uint32_t ko = (uint32_t)ks * 32u;
                uint32_t afh[2][4], afl[2][4];
                ldsm_x4(ah0 + ko, afh[0]);
                ldsm_x4(ah1 + ko, afh[1]);
                ldsm_x4(al0 + ko, afl[0]);
                ldsm_x4(al1 + ko, afl[1]);
#pragma unroll
                for (int nt = 0; nt < 4; nt++) {
                    const uint32_t boff = (uint32_t)(nt * 8 * RS) * 2u + ko;
                    uint32_t bfh[2], bfl[2];
                    ldsm_x2(bph + boff, bfh);
                    ldsm_x2(bpl + boff, bfl);
#pragma unroll
                    for (int mt = 0; mt < 2; mt++) {
                        mma_bf16(acc[mt][nt], afh[mt], bfh);
                        mma_bf16(acc[mt][nt], afh[mt], bfl);
                        mma_bf16(acc[mt][nt], afl[mt], bfh);
                    }
                }
            }

#pragma unroll
            for (int mt = 0; mt < 2; mt++) {
                const int row = row0 + 32 * mg + 16 * mt + gid;
#pragma unroll
                for (int nt = 0; nt < 4; nt++) {
                    const int col = n0 + 32 * ng + 8 * nt + tig * 2;
                    float2 bv = *reinterpret_cast<const float2*>(&bs[col]);
                    float2 v0 = make_float2(acc[mt][nt][0] + bv.x, acc[mt][nt][1] + bv.y);
                    float2 v1 = make_float2(acc[mt][nt][2] + bv.x, acc[mt][nt][3] + bv.y);
                    *reinterpret_cast<float2*>(&outp[(size_t)row * Hh + col])       = v0;
                    *reinterpret_cast<float2*>(&outp[(size_t)(row + 8) * Hh + col]) = v1;
                }
            }
        }
    }
}

// ---------------------------------------------------------------------------
// Cluster scan (R11, best validated — only change: tanhf -> fast_tanh)
// ---------------------------------------------------------------------------
#define UH_OFF   0
#define HT_OFF   16384
#define RHT_OFF  (HT_OFF + 288)
#define INZR_OFF (RHT_OFF + 288)
#define INH_OFF  (INZR_OFF + 2048)
#define MBAR_OFF (INH_OFF + 1024)
#define SMEM_FLOATS (MBAR_OFF + 4)

__global__ void __cluster_dims__(4, 1, 1) __launch_bounds__(512, 1)
scan_cluster_kernel(const float* __restrict__ Uz, const float* __restrict__ Ur,
                    const float* __restrict__ Uh, float* __restrict__ out)
{
    extern __shared__ float sm[];
    const int tid  = threadIdx.x;
    const int rank = (int)ctarank_();
    const int cluster_id = blockIdx.x >> 2;

    const uint32_t mbzr = smem_u32(&sm[MBAR_OFF]);
    const uint32_t mbh  = smem_u32(&sm[MBAR_OFF + 2]);

    for (int i = tid; i < 64 * 64; i += 512) {
        int k = i >> 6, c = (i & 63) * 4;
        int cs = (c + ((k >> 3) & 7) * 4) & 255;
        *reinterpret_cast<float4*>(&sm[UH_OFF + k * 256 + cs]) =
            *reinterpret_cast<const float4*>(&Uh[(size_t)(64 * rank + k) * Hh + c]);
    }
    if (tid < 256) {
        int k = tid >> 2, b = tid & 3;
        sm[HT_OFF + k * 4 + ((k >> 4) & 3) * 8 + b] = 0.0f;
    }
    if (tid == 0) {
        asm volatile("mbarrier.init.shared.b64 [%0], %1;" :: "r"(mbzr), "r"(16) : "memory");
        asm volatile("mbarrier.init.shared.b64 [%0], %1;" :: "r"(mbh),  "r"(16) : "memory");
    }

    const int gate = tid >> 8;
    const int p1cg = (tid & 255) >> 2;
    const int p1k  = tid & 3;
    const int p1c0 = p1cg * 4;
    const int p1dst = p1cg >> 4;
    const int p1cl  = (p1cg & 15) * 4;
    const int p1hb  = HT_OFF + p1k * 72;

    float4 Ug[16];
    {
        const float* Usrc = gate ? Ur : Uz;
#pragma unroll
        for (int kk = 0; kk < 16; kk++)
            Ug[kk] = *reinterpret_cast<const float4*>(
                &Usrc[(size_t)(64 * rank + p1k * 16 + kk) * Hh + p1c0]);
    }

    const int p2cg = tid >> 3;
    const int p2k  = tid & 7;
    const int p2crot = (p2cg * 4 + p2k * 4) & 255;
    const int p2dst  = p2cg >> 4;
    const int p2cl   = (p2cg & 15) * 4;
    const int p2hb   = RHT_OFF + 32 * p2k + 8 * (p2k >> 1);

    const int rtid  = tid & 255;
    const int rb    = rtid >> 6;
    const int rcl   = rtid & 63;
    const int rswz  = rcl * 4 + ((rcl >> 4) & 3) * 8;
    const int cglob = rank * 64 + rcl;
    const int bglob = cluster_id * 4 + rb;
    const size_t xbase = ((size_t)bglob * Tt) * Hh + cglob;

    const uint32_t inzr_base = smem_u32(&sm[INZR_OFF]);
    const uint32_t inh_base  = smem_u32(&sm[INH_OFF]);

    float h_reg = 0.0f, zkeep = 0.0f;

    float xz_c = 0.f, xr_c = 0.f, xh_c = 0.f;
    if (tid < 256) { xz_c = g_xz[xbase]; xh_c = g_xh[xbase]; }
    else           { xr_c = g_xr[xbase]; }

    __syncthreads();
    cluster_sync_();

#pragma unroll 1
    for (int t = 0; t < Tt; t++) {
        const uint32_t ph = (uint32_t)(t & 1);

        float xz_n = 0.f, xr_n = 0.f, xh_n = 0.f;
        {
            const int tn = (t + 1 < Tt) ? (t + 1) : t;
            const size_t xoff = xbase + (size_t)tn * Hh;
            if (tid < 256) { xz_n = g_xz[xoff]; xh_n = g_xh[xoff]; }
            else           { xr_n = g_xr[xoff]; }
        }
        const float xzv = xz_c, xrv = xr_c, xhv = xh_c;

        float2 v[8];
#pragma unroll
        for (int j = 0; j < 8; j++) v[j] = make_float2(0.f, 0.f);
#pragma unroll
        for (int kk = 0; kk < 16; kk++) {
            float4 h4 = *reinterpret_cast<const float4*>(&sm[p1hb + kk * 4]);
            float2 u01 = make_float2(Ug[kk].x, Ug[kk].y);
            float2 u23 = make_float2(Ug[kk].z, Ug[kk].w);
            const float hb[4] = {h4.x, h4.y, h4.z, h4.w};
#pragma unroll
            for (int b = 0; b < 4; b++) {
                float2 h2 = make_float2(hb[b], hb[b]);
                v[2 * b]     = ffma2(u01, h2, v[2 * b]);
                v[2 * b + 1] = ffma2(u23, h2, v[2 * b + 1]);
            }
        }
        {
            const bool hi2 = (p1k >> 1) & 1;
#pragma unroll
            for (int j = 0; j < 4; j++) {
                float sx = hi2 ? v[j].x : v[j + 4].x;
                float sy = hi2 ? v[j].y : v[j + 4].y;
                float rx = __shfl_xor_sync(0xffffffffu, sx, 2);
                float ry = __shfl_xor_sync(0xffffffffu, sy, 2);
                if (hi2) { v[j + 4].x += rx; v[j + 4].y += ry; }
                else     { v[j].x     += rx; v[j].y     += ry; }
            }
            float2 w[4];
#pragma unroll
            for (int j = 0; j < 4; j++) {
                w[j].x = hi2 ? v[j + 4].x : v[j].x;
                w[j].y = hi2 ? v[j + 4].y : v[j].y;
            }
            const bool hi1 = p1k & 1;
#pragma unroll
            for (int j = 0; j < 2; j++) {
                float sx = hi1 ? w[j].x : w[j + 2].x;
                float sy = hi1 ? w[j].y : w[j + 2].y;
                float rx = __shfl_xor_sync(0xffffffffu, sx, 1);
                float ry = __shfl_xor_sync(0xffffffffu, sy, 1);
                if (hi1) { w[j + 2].x += rx; w[j + 2].y += ry; }
                else     { w[j].x     += rx; w[j].y     += ry; }
            }
            float2 f0, f1;
            f0.x = hi1 ? w[2].x : w[0].x;  f0.y = hi1 ? w[2].y : w[0].y;
            f1.x = hi1 ? w[3].x : w[1].x;  f1.y = hi1 ? w[3].y : w[1].y;
            uint32_t addr = inzr_base +
                (uint32_t)((((rank * 2 + gate) * 4 + p1k) * 64 + p1cl) * 4);
            st_remote_f4(addr, p1dst, make_float4(f0.x, f0.y, f1.x, f1.y));
        }
        __syncwarp();
        if ((tid & 31) == 0) mbar_arrive_remote(mbzr, p1dst);

        mbar_wait_parity(mbzr, ph);
        if (tid < 256) {
            float sz = xzv;
#pragma unroll
            for (int s = 0; s < 4; s++)
                sz += sm[INZR_OFF + ((s * 2 + 0) * 4 + rb) * 64 + rcl];
            zkeep = hsig(sz);
        } else {
            float sr = xrv;
#pragma unroll
            for (int s = 0; s < 4; s++)
                sr += sm[INZR_OFF + ((s * 2 + 1) * 4 + rb) * 64 + rcl];
            const float r = hsig(sr);
            const float hprev = sm[HT_OFF + rswz + rb];
            sm[RHT_OFF + rswz + rb] = r * hprev;
        }
        __syncthreads();

#pragma unroll
        for (int j = 0; j < 8; j++) v[j] = make_float2(0.f, 0.f);
#pragma unroll
        for (int kk = 0; kk < 8; kk++) {
            const int krow = (p2k * 8 + kk) * 256 + p2crot;
            float4 uh = *reinterpret_cast<const float4*>(&sm[UH_OFF + krow]);
            float4 r4 = *reinterpret_cast<const float4*>(&sm[p2hb + kk * 4]);
            float2 u01 = make_float2(uh.x, uh.y);
            float2 u23 = make_float2(uh.z, uh.w);
            const float rv[4] = {r4.x, r4.y, r4.z, r4.w};
#pragma unroll
            for (int b = 0; b < 4; b++) {
                float2 r2 = make_float2(rv[b], rv[b]);
                v[2 * b]     = ffma2(u01, r2, v[2 * b]);
                v[2 * b + 1] = ffma2(u23, r2, v[2 * b + 1]);
            }
        }
        {
            const bool h4b = (p2k >> 2) & 1;
#pragma unroll
            for (int j = 0; j < 4; j++) {
                float sx = h4b ? v[j].x : v[j + 4].x;
                float sy = h4b ? v[j].y : v[j + 4].y;
                float rx = __shfl_xor_sync(0xffffffffu, sx, 4);
                float ry = __shfl_xor_sync(0xffffffffu, sy, 4);
                if (h4b) { v[j + 4].x += rx; v[j + 4].y += ry; }
                else     { v[j].x     += rx; v[j].y     += ry; }
            }
            float2 w[4];
#pragma unroll
            for (int j = 0; j < 4; j++) {
                w[j].x = h4b ? v[j + 4].x : v[j].x;
                w[j].y = h4b ? v[j + 4].y : v[j].y;
            }
            const bool h2b = (p2k >> 1) & 1;
#pragma unroll
            for (int j = 0; j < 2; j++) {
                float sx = h2b ? w[j].x : w[j + 2].x;
                float sy = h2b ? w[j].y : w[j + 2].y;
                float rx = __shfl_xor_sync(0xffffffffu, sx, 2);
                float ry = __shfl_xor_sync(0xffffffffu, sy, 2);
                if (h2b) { w[j + 2].x += rx; w[j + 2].y += ry; }
                else     { w[j].x     += rx; w[j].y     += ry; }
            }
            float2 u0, u1;
            u0.x = h2b ? w[2].x : w[0].x;  u0.y = h2b ? w[2].y : w[0].y;
            u1.x = h2b ? w[3].x : w[1].x;  u1.y = h2b ? w[3].y : w[1].y;
            const bool h1b = p2k & 1;
            {
                float sx = h1b ? u0.x : u1.x;
                float sy = h1b ? u0.y : u1.y;
                float rx = __shfl_xor_sync(0xffffffffu, sx, 1);
                float ry = __shfl_xor_sync(0xffffffffu, sy, 1);
                if (h1b) { u1.x += rx; u1.y += ry; }
                else     { u0.x += rx; u0.y += ry; }
            }
            float2 fin;
            fin.x = h1b ? u1.x : u0.x;
            fin.y = h1b ? u1.y : u0.y;
            uint32_t addr = inh_base +
                (uint32_t)(((rank * 4 + (p2k >> 1)) * 64 + p2cl + (p2k & 1) * 2) * 4);
            st_remote_f2(addr, p2dst, fin);
        }
        __syncwarp();
        if ((tid & 31) == 0) mbar_arrive_remote(mbh, p2dst);

        if (tid < 256) {
            mbar_wait_parity(mbh, ph);
            float sh = xhv;
#pragma unroll
            for (int s = 0; s < 4; s++)
                sh += sm[INH_OFF + (s * 4 + rb) * 64 + rcl];
            const float hh = fast_tanh(sh);
            h_reg = zkeep * h_reg + (1.0f - zkeep) * hh;
            sm[HT_OFF + rswz + rb] = h_reg;
        }
        __syncthreads();

        xz_c = xz_n; xr_c = xr_n; xh_c = xh_n;
    }

    if (tid < 256)
        out[(size_t)bglob * Hh + cglob] = h_reg;

    cluster_sync_();
}

extern "C" void kernel_launch(void* const* d_in, const int* in_sizes, int n_in,
                              void* d_out, int out_size) {
    (void)in_sizes; (void)n_in; (void)out_size;
    const float* x  = (const float*)d_in[0];
    const float* Wz = (const float*)d_in[1];
    const float* Wr = (const float*)d_in[2];
    const float* Wh = (const float*)d_in[3];
    const float* Uz = (const float*)d_in[4];
    const float* Ur = (const float*)d_in[5];
    const float* Uh = (const float*)d_in[6];
    const float* bz = (const float*)d_in[7];
    const float* br = (const float*)d_in[8];
    const float* bh = (const float*)d_in[9];
    float* out = (float*)d_out;

    static int smem_set = 0;
    if (!smem_set) {
        cudaFuncSetAttribute(scan_cluster_kernel,
                             cudaFuncAttributeMaxDynamicSharedMemorySize,
                             SMEM_FLOATS * sizeof(float));
        cudaFuncSetAttribute(proj_mma_kernel,
                             cudaFuncAttributeMaxDynamicSharedMemorySize,
                             PROJ_SMEM_BYTES);
        smem_set = 1;
    }

    proj_mma_kernel<<<BT / 128, 256, PROJ_SMEM_BYTES>>>(x, Wz, Wr, Wh, bz, br, bh);
    scan_cluster_kernel<<<Bb, 512, SMEM_FLOATS * sizeof(float)>>>(Uz, Ur, Uh, out);
}

// round 16
// speedup vs baseline: 1.2876x; 1.0150x over previous
#include <cuda_runtime.h>
#include <cuda_bf16.h>
#include <cstdint>

#define Bb   128
#define Tt   1024
#define Dd   256
#define Hh   256
#define BT   (Bb * Tt)

__device__ float g_xz[(size_t)BT * Hh];
__device__ float g_xr[(size_t)BT * Hh];
__device__ float g_xh[(size_t)BT * Hh];

__device__ __forceinline__ float2 ffma2(float2 a, float2 b, float2 c) {
    float2 d;
    asm("fma.rn.f32x2 %0, %1, %2, %3;"
        : "=l"(*reinterpret_cast<unsigned long long*>(&d))
        : "l"(*reinterpret_cast<const unsigned long long*>(&a)),
          "l"(*reinterpret_cast<const unsigned long long*>(&b)),
          "l"(*reinterpret_cast<const unsigned long long*>(&c)));
    return d;
}

__device__ __forceinline__ float hsig(float x) {
    return fminf(fmaxf(fmaf(x, 0.2f, 0.5f), 0.0f), 1.0f);
}

// Branch-free tanh via MUFU: tanh(x) = 1 - 2/(e^{2x}+1).
__device__ __forceinline__ float fast_tanh(float x) {
    const float e = __expf(2.0f * x);
    return 1.0f - __fdividef(2.0f, e + 1.0f);
}

__device__ __forceinline__ uint32_t smem_u32(const void* p) {
    uint32_t a;
    asm("{ .reg .u64 t; cvta.to.shared.u64 t, %1; cvt.u32.u64 %0, t; }"
        : "=r"(a) : "l"(p));
    return a;
}

__device__ __forceinline__ void st_remote_f4(uint32_t laddr, int rank, float4 v) {
    uint32_t raddr;
    asm volatile("mapa.shared::cluster.u32 %0, %1, %2;"
                 : "=r"(raddr) : "r"(laddr), "r"(rank));
    asm volatile("st.shared::cluster.v4.f32 [%0], {%1, %2, %3, %4};"
                 :: "r"(raddr), "f"(v.x), "f"(v.y), "f"(v.z), "f"(v.w) : "memory");
}

__device__ __forceinline__ void st_remote_f2(uint32_t laddr, int rank, float2 v) {
    uint32_t raddr;
    asm volatile("mapa.shared::cluster.u32 %0, %1, %2;"
                 : "=r"(raddr) : "r"(laddr), "r"(rank));
    asm volatile("st.shared::cluster.v2.f32 [%0], {%1, %2};"
                 :: "r"(raddr), "f"(v.x), "f"(v.y) : "memory");
}

__device__ __forceinline__ void cluster_sync_() {
    asm volatile("barrier.cluster.arrive.aligned;" ::: "memory");
    asm volatile("barrier.cluster.wait.aligned;" ::: "memory");
}

__device__ __forceinline__ uint32_t ctarank_() {
    uint32_t r;
    asm("mov.u32 %0, %%cluster_ctarank;" : "=r"(r));
    return r;
}

__device__ __forceinline__ void mbar_arrive_remote(uint32_t laddr, int rank) {
    uint32_t raddr;
    asm volatile("mapa.shared::cluster.u32 %0, %1, %2;"
                 : "=r"(raddr) : "r"(laddr), "r"(rank));
    asm volatile("mbarrier.arrive.release.cluster.shared::cluster.b64 _, [%0];"
                 :: "r"(raddr) : "memory");
}

__device__ __forceinline__ void mbar_wait_parity(uint32_t addr, uint32_t parity) {
    asm volatile(
        "{\n\t"
        ".reg .pred P;\n\t"
        "WL_%=:\n\t"
        "mbarrier.try_wait.parity.acquire.cluster.shared::cta.b64 P, [%0], %1, 0x989680;\n\t"
        "@!P bra WL_%=;\n\t"
        "}"
        :: "r"(addr), "r"(parity) : "memory");
}

// ---------------------------------------------------------------------------
// HMMA projection R16: 512 threads, 16 warps, warp tile m16 x n32.
// Same math / accumulation order as R9 (bit-identical output); double the
// warps per SMSP to cover ldsm->HMMA latency (proj was ~11% issue-efficient).
// ---------------------------------------------------------------------------
#define RS     264
#define PA_HI  0
#define PA_LO  67584
#define PB_HI  135168
#define PB_LO  168960
#define PROJ_SMEM_BYTES 202752

__device__ __forceinline__ void ldsm_x4(uint32_t addr, uint32_t* r) {
    asm volatile("ldmatrix.sync.aligned.m8n8.x4.shared.b16 {%0,%1,%2,%3}, [%4];"
                 : "=r"(r[0]), "=r"(r[1]), "=r"(r[2]), "=r"(r[3]) : "r"(addr));
}
__device__ __forceinline__ void ldsm_x2(uint32_t addr, uint32_t* r) {
    asm volatile("ldmatrix.sync.aligned.m8n8.x2.shared.b16 {%0,%1}, [%2];"
                 : "=r"(r[0]), "=r"(r[1]) : "r"(addr));
}
__device__ __forceinline__ void mma_bf16(float* c, const uint32_t* a, const uint32_t* b) {
    asm volatile(
        "mma.sync.aligned.m16n8k16.row.col.f32.bf16.bf16.f32 "
        "{%0,%1,%2,%3}, {%4,%5,%6,%7}, {%8,%9}, {%0,%1,%2,%3};"
        : "+f"(c[0]), "+f"(c[1]), "+f"(c[2]), "+f"(c[3])
        : "r"(a[0]), "r"(a[1]), "r"(a[2]), "r"(a[3]), "r"(b[0]), "r"(b[1]));
}

__global__ __launch_bounds__(512, 1) void proj_mma_kernel(
    const float* __restrict__ x,
    const float* __restrict__ Wz, const float* __restrict__ Wr,
    const float* __restrict__ Wh,
    const float* __restrict__ bz, const float* __restrict__ br,
    const float* __restrict__ bh)
{
    extern __shared__ char dsm[];
    const uint32_t sbase = smem_u32(dsm);

    const int tid  = threadIdx.x;
    const int wid  = tid >> 5;
    const int lane = tid & 31;
    const int row0 = blockIdx.x * 128;
    const int mg   = wid >> 1;          // 0..7 (m-group of 16 rows)
    const int ng   = wid & 1;           // 0..1 (n-group of 32 cols)

    // ---- convert x tile -> A_hi / A_lo ----
    for (int idx = tid; idx < 128 * 64; idx += 512) {
        int m = idx >> 6, kq = (idx & 63) << 2;
        float4 v = *reinterpret_cast<const float4*>(&x[(size_t)(row0 + m) * Dd + kq]);
        __nv_bfloat16 h0 = __float2bfloat16(v.x), h1 = __float2bfloat16(v.y);
        __nv_bfloat16 h2 = __float2bfloat16(v.z), h3 = __float2bfloat16(v.w);
        __nv_bfloat16 l0 = __float2bfloat16(v.x - __bfloat162float(h0));
        __nv_bfloat16 l1 = __float2bfloat16(v.y - __bfloat162float(h1));
        __nv_bfloat16 l2 = __float2bfloat16(v.z - __bfloat162float(h2));
        __nv_bfloat16 l3 = __float2bfloat16(v.w - __bfloat162float(h3));
        uint32_t off = (uint32_t)(m * RS + kq) * 2u;
        *reinterpret_cast<__nv_bfloat162*>(dsm + PA_HI + off)     = __halves2bfloat162(h0, h1);
        *reinterpret_cast<__nv_bfloat162*>(dsm + PA_HI + off + 4) = __halves2bfloat162(h2, h3);
        *reinterpret_cast<__nv_bfloat162*>(dsm + PA_LO + off)     = __halves2bfloat162(l0, l1);
        *reinterpret_cast<__nv_bfloat162*>(dsm + PA_LO + off + 4) = __halves2bfloat162(l2, l3);
    }

    // ---- ldmatrix lane pointers ----
    const int arow = 16 * mg + (lane & 15);
    const int ako  = (lane >> 4) * 8;
    const uint32_t aph = sbase + PA_HI + (uint32_t)(arow * RS + ako) * 2u;
    const uint32_t apl = sbase + PA_LO + (uint32_t)(arow * RS + ako) * 2u;

    const int nrow = 32 * ng + (lane & 7);
    const int bko  = (lane & 8) ? 8 : 0;
    const uint32_t bph = sbase + PB_HI + (uint32_t)(nrow * RS + bko) * 2u;
    const uint32_t bpl = sbase + PB_LO + (uint32_t)(nrow * RS + bko) * 2u;

    const int gid = lane >> 2;
    const int tig = lane & 3;

    for (int g = 0; g < 3; g++) {
        const float* W  = (g == 0) ? Wz : (g == 1) ? Wr : Wh;
        const float* bs = (g == 0) ? bz : (g == 1) ? br : bh;
        float* outp     = (g == 0) ? g_xz : (g == 1) ? g_xr : g_xh;

        for (int nc = 0; nc < 4; nc++) {
            const int n0 = nc * 64;
            __syncthreads();   // prior chunk's ldmatrix reads complete

            // ---- load + convert B chunk: B[n][k] = W[k][n0+n], pack k-pairs ----
            for (int idx = tid; idx < 64 * 128; idx += 512) {
                int k2 = idx >> 6;
                int n  = idx & 63;
                float w0 = W[(size_t)(2 * k2) * Hh + n0 + n];
                float w1 = W[(size_t)(2 * k2 + 1) * Hh + n0 + n];
                __nv_bfloat16 h0 = __float2bfloat16(w0);
                __nv_bfloat16 h1 = __float2bfloat16(w1);
                __nv_bfloat16 l0 = __float2bfloat16(w0 - __bfloat162float(h0));
                __nv_bfloat16 l1 = __float2bfloat16(w1 - __bfloat162float(h1));
                uint32_t off = (uint32_t)(n * RS + 2 * k2) * 2u;
                *reinterpret_cast<__nv_bfloat162*>(dsm + PB_HI + off) = __halves2bfloat162(h0, h1);
                *reinterpret_cast<__nv_bfloat162*>(dsm + PB_LO + off) = __halves2bfloat162(l0, l1);
            }
            __syncthreads();

            // ---- MMA mainloop (m16n32 per warp) ----
            float acc[4][4];
#pragma unroll
            for (int nt = 0; nt < 4; nt++)
#pragma unroll
                for (int j = 0; j < 4; j++) acc[nt][j] = 0.0f;

#pragma unroll 4
            for (int ks = 0; ks < 16; ks++) {
                const uint32_t ko = (uint32_t)ks * 32u;
                uint32_t afh[4], afl[4];
                ldsm_x4(aph + ko, afh);
                ldsm_x4(apl + ko, afl);
#pragma unroll
                for (int nt = 0; nt < 4; nt++) {
                    const uint32_t boff = (uint32_t)(nt * 8 * RS) * 2u + ko;
                    uint32_t bfh[2], bfl[2];
                    ldsm_x2(bph + boff, bfh);
                    ldsm_x2(bpl + boff, bfl);
                    mma_bf16(acc[nt], afh, bfh);
                    mma_bf16(acc[nt], afh, bfl);
                    mma_bf16(acc[nt], afl, bfh);
                }
            }

            // ---- epilogue: bias + direct STG ----
            const int row = row0 + 16 * mg + gid;
#pragma unroll
            for (int nt = 0; nt < 4; nt++) {
                const int col = n0 + 32 * ng + 8 * nt + tig * 2;
                float2 bv = *reinterpret_cast<const float2*>(&bs[col]);
                float2 v0 = make_float2(acc[nt][0] + bv.x, acc[nt][1] + bv.y);
                float2 v1 = make_float2(acc[nt][2] + bv.x, acc[nt][3] + bv.y);
                *reinterpret_cast<float2*>(&outp[(size_t)row * Hh + col])       = v0;
                *reinterpret_cast<float2*>(&outp[(size_t)(row + 8) * Hh + col]) = v1;
            }
        }
    }
}

// ---------------------------------------------------------------------------
// Cluster scan (identical to R15 — best, 5x validated flow + fast_tanh)
// ---------------------------------------------------------------------------
#define UH_OFF   0
#define HT_OFF   16384
#define RHT_OFF  (HT_OFF + 288)
#define INZR_OFF (RHT_OFF + 288)
#define INH_OFF  (INZR_OFF + 2048)
#define MBAR_OFF (INH_OFF + 1024)
#define SMEM_FLOATS (MBAR_OFF + 4)

__global__ void __cluster_dims__(4, 1, 1) __launch_bounds__(512, 1)
scan_cluster_kernel(const float* __restrict__ Uz, const float* __restrict__ Ur,
                    const float* __restrict__ Uh, float* __restrict__ out)
{
    extern __shared__ float sm[];
    const int tid  = threadIdx.x;
    const int rank = (int)ctarank_();
    const int cluster_id = blockIdx.x >> 2;

    const uint32_t mbzr = smem_u32(&sm[MBAR_OFF]);
    const uint32_t mbh  = smem_u32(&sm[MBAR_OFF + 2]);

    for (int i = tid; i < 64 * 64; i += 512) {
        int k = i >> 6, c = (i & 63) * 4;
        int cs = (c + ((k >> 3) & 7) * 4) & 255;
        *reinterpret_cast<float4*>(&sm[UH_OFF + k * 256 + cs]) =
            *reinterpret_cast<const float4*>(&Uh[(size_t)(64 * rank + k) * Hh + c]);
    }
    if (tid < 256) {
        int k = tid >> 2, b = tid & 3;
        sm[HT_OFF + k * 4 + ((k >> 4) & 3) * 8 + b] = 0.0f;
    }
    if (tid == 0) {
        asm volatile("mbarrier.init.shared.b64 [%0], %1;" :: "r"(mbzr), "r"(16) : "memory");
        asm volatile("mbarrier.init.shared.b64 [%0], %1;" :: "r"(mbh),  "r"(16) : "memory");
    }

    const int gate = tid >> 8;
    const int p1cg = (tid & 255) >> 2;
    const int p1k  = tid & 3;
    const int p1c0 = p1cg * 4;
    const int p1dst = p1cg >> 4;
    const int p1cl  = (p1cg & 15) * 4;
    const int p1hb  = HT_OFF + p1k * 72;

    float4 Ug[16];
    {
        const float* Usrc = gate ? Ur : Uz;
#pragma unroll
        for (int kk = 0; kk < 16; kk++)
            Ug[kk] = *reinterpret_cast<const float4*>(
                &Usrc[(size_t)(64 * rank + p1k * 16 + kk) * Hh + p1c0]);
    }

    const int p2cg = tid >> 3;
    const int p2k  = tid & 7;
    const int p2crot = (p2cg * 4 + p2k * 4) & 255;
    const int p2dst  = p2cg >> 4;
    const int p2cl   = (p2cg & 15) * 4;
    const int p2hb   = RHT_OFF + 32 * p2k + 8 * (p2k >> 1);

    const int rtid  = tid & 255;
    const int rb    = rtid >> 6;
    const int rcl   = rtid & 63;
    const int rswz  = rcl * 4 + ((rcl >> 4) & 3) * 8;
    const int cglob = rank * 64 + rcl;
    const int bglob = cluster_id * 4 + rb;
    const size_t xbase = ((size_t)bglob * Tt) * Hh + cglob;

    const uint32_t inzr_base = smem_u32(&sm[INZR_OFF]);
    const uint32_t inh_base  = smem_u32(&sm[INH_OFF]);

    float h_reg = 0.0f, zkeep = 0.0f;

    float xz_c = 0.f, xr_c = 0.f, xh_c = 0.f;
    if (tid < 256) { xz_c = g_xz[xbase]; xh_c = g_xh[xbase]; }
    else           { xr_c = g_xr[xbase]; }

    __syncthreads();
    cluster_sync_();

#pragma unroll 1
    for (int t = 0; t < Tt; t++) {
        const uint32_t ph = (uint32_t)(t & 1);

        float xz_n = 0.f, xr_n = 0.f, xh_n = 0.f;
        {
            const int tn = (t + 1 < Tt) ? (t + 1) : t;
            const size_t xoff = xbase + (size_t)tn * Hh;
            if (tid < 256) { xz_n = g_xz[xoff]; xh_n = g_xh[xoff]; }
            else           { xr_n = g_xr[xoff]; }
        }
        const float xzv = xz_c, xrv = xr_c, xhv = xh_c;

        float2 v[8];
#pragma unroll
        for (int j = 0; j < 8; j++) v[j] = make_float2(0.f, 0.f);
#pragma unroll
        for (int kk = 0; kk < 16; kk++) {
            float4 h4 = *reinterpret_cast<const float4*>(&sm[p1hb + kk * 4]);
            float2 u01 = make_float2(Ug[kk].x, Ug[kk].y);
            float2 u23 = make_float2(Ug[kk].z, Ug[kk].w);
            const float hb[4] = {h4.x, h4.y, h4.z, h4.w};
#pragma unroll
            for (int b = 0; b < 4; b++) {
                float2 h2 = make_float2(hb[b], hb[b]);
                v[2 * b]     = ffma2(u01, h2, v[2 * b]);
                v[2 * b + 1] = ffma2(u23, h2, v[2 * b + 1]);
            }
        }
        {
            const bool hi2 = (p1k >> 1) & 1;
#pragma unroll
            for (int j = 0; j < 4; j++) {
                float sx = hi2 ? v[j].x : v[j + 4].x;
                float sy = hi2 ? v[j].y : v[j + 4].y;
                float rx = __shfl_xor_sync(0xffffffffu, sx, 2);
                float ry = __shfl_xor_sync(0xffffffffu, sy, 2);
                if (hi2) { v[j + 4].x += rx; v[j + 4].y += ry; }
                else     { v[j].x     += rx; v[j].y     += ry; }
            }
            float2 w[4];
#pragma unroll
            for (int j = 0; j < 4; j++) {
                w[j].x = hi2 ? v[j + 4].x : v[j].x;
                w[j].y = hi2 ? v[j + 4].y : v[j].y;
            }
            const bool hi1 = p1k & 1;
#pragma unroll
            for (int j = 0; j < 2; j++) {
                float sx = hi1 ? w[j].x : w[j + 2].x;
                float sy = hi1 ? w[j].y : w[j + 2].y;
                float rx = __shfl_xor_sync(0xffffffffu, sx, 1);
                float ry = __shfl_xor_sync(0xffffffffu, sy, 1);
                if (hi1) { w[j + 2].x += rx; w[j + 2].y += ry; }
                else     { w[j].x     += rx; w[j].y     += ry; }
            }
            float2 f0, f1;
            f0.x = hi1 ? w[2].x : w[0].x;  f0.y = hi1 ? w[2].y : w[0].y;
            f1.x = hi1 ? w[3].x : w[1].x;  f1.y = hi1 ? w[3].y : w[1].y;
            uint32_t addr = inzr_base +
                (uint32_t)((((rank * 2 + gate) * 4 + p1k) * 64 + p1cl) * 4);
            st_remote_f4(addr, p1dst, make_float4(f0.x, f0.y, f1.x, f1.y));
        }
        __syncwarp();
        if ((tid & 31) == 0) mbar_arrive_remote(mbzr, p1dst);

        mbar_wait_parity(mbzr, ph);
        if (tid < 256) {
            float sz = xzv;
#pragma unroll
            for (int s = 0; s < 4; s++)
                sz += sm[INZR_OFF + ((s * 2 + 0) * 4 + rb) * 64 + rcl];
            zkeep = hsig(sz);
        } else {
            float sr = xrv;
#pragma unroll
            for (int s = 0; s < 4; s++)
                sr += sm[INZR_OFF + ((s * 2 + 1) * 4 + rb) * 64 + rcl];
            const float r = hsig(sr);
            const float hprev = sm[HT_OFF + rswz + rb];
            sm[RHT_OFF + rswz + rb] = r * hprev;
        }
        __syncthreads();

#pragma unroll
        for (int j = 0; j < 8; j++) v[j] = make_float2(0.f, 0.f);
#pragma unroll
        for (int kk = 0; kk < 8; kk++) {
            const int krow = (p2k * 8 + kk) * 256 + p2crot;
            float4 uh = *reinterpret_cast<const float4*>(&sm[UH_OFF + krow]);
            float4 r4 = *reinterpret_cast<const float4*>(&sm[p2hb + kk * 4]);
            float2 u01 = make_float2(uh.x, uh.y);
            float2 u23 = make_float2(uh.z, uh.w);
            const float rv[4] = {r4.x, r4.y, r4.z, r4.w};
#pragma unroll
            for (int b = 0; b < 4; b++) {
                float2 r2 = make_float2(rv[b], rv[b]);
                v[2 * b]     = ffma2(u01, r2, v[2 * b]);
                v[2 * b + 1] = ffma2(u23, r2, v[2 * b + 1]);
            }
        }
        {
            const bool h4b = (p2k >> 2) & 1;
#pragma unroll
            for (int j = 0; j < 4; j++) {
                float sx = h4b ? v[j].x : v[j + 4].x;
                float sy = h4b ? v[j].y : v[j + 4].y;
                float rx = __shfl_xor_sync(0xffffffffu, sx, 4);
                float ry = __shfl_xor_sync(0xffffffffu, sy, 4);
                if (h4b) { v[j + 4].x += rx; v[j + 4].y += ry; }
                else     { v[j].x     += rx; v[j].y     += ry; }
            }
            float2 w[4];
#pragma unroll
            for (int j = 0; j < 4; j++) {
                w[j].x = h4b ? v[j + 4].x : v[j].x;
                w[j].y = h4b ? v[j + 4].y : v[j].y;
            }
            const bool h2b = (p2k >> 1) & 1;
#pragma unroll
            for (int j = 0; j < 2; j++) {
                float sx = h2b ? w[j].x : w[j + 2].x;
                float sy = h2b ? w[j].y : w[j + 2].y;
                float rx = __shfl_xor_sync(0xffffffffu, sx, 2);
                float ry = __shfl_xor_sync(0xffffffffu, sy, 2);
                if (h2b) { w[j + 2].x += rx; w[j + 2].y += ry; }
                else     { w[j].x     += rx; w[j].y     += ry; }
            }
            float2 u0, u1;
            u0.x = h2b ? w[2].x : w[0].x;  u0.y = h2b ? w[2].y : w[0].y;
            u1.x = h2b ? w[3].x : w[1].x;  u1.y = h2b ? w[3].y : w[1].y;
            const bool h1b = p2k & 1;
            {
                float sx = h1b ? u0.x : u1.x;
                float sy = h1b ? u0.y : u1.y;
                float rx = __shfl_xor_sync(0xffffffffu, sx, 1);
                float ry = __shfl_xor_sync(0xffffffffu, sy, 1);
                if (h1b) { u1.x += rx; u1.y += ry; }
                else     { u0.x += rx; u0.y += ry; }
            }
            float2 fin;
            fin.x = h1b ? u1.x : u0.x;
            fin.y = h1b ? u1.y : u0.y;
            uint32_t addr = inh_base +
                (uint32_t)(((rank * 4 + (p2k >> 1)) * 64 + p2cl + (p2k & 1) * 2) * 4);
            st_remote_f2(addr, p2dst, fin);
        }
        __syncwarp();
        if ((tid & 31) == 0) mbar_arrive_remote(mbh, p2dst);

        if (tid < 256) {
            mbar_wait_parity(mbh, ph);
            float sh = xhv;
#pragma unroll
            for (int s = 0; s < 4; s++)
                sh += sm[INH_OFF + (s * 4 + rb) * 64 + rcl];
            const float hh = fast_tanh(sh);
            h_reg = zkeep * h_reg + (1.0f - zkeep) * hh;
            sm[HT_OFF + rswz + rb] = h_reg;
        }
        __syncthreads();

        xz_c = xz_n; xr_c = xr_n; xh_c = xh_n;
    }

    if (tid < 256)
        out[(size_t)bglob * Hh + cglob] = h_reg;

    cluster_sync_();
}

extern "C" void kernel_launch(void* const* d_in, const int* in_sizes, int n_in,
                              void* d_out, int out_size) {
    (void)in_sizes; (void)n_in; (void)out_size;
    const float* x  = (const float*)d_in[0];
    const float* Wz = (const float*)d_in[1];
    const float* Wr = (const float*)d_in[2];
    const float* Wh = (const float*)d_in[3];
    const float* Uz = (const float*)d_in[4];
    const float* Ur = (const float*)d_in[5];
    const float* Uh = (const float*)d_in[6];
    const float* bz = (const float*)d_in[7];
    const float* br = (const float*)d_in[8];
    const float* bh = (const float*)d_in[9];
    float* out = (float*)d_out;

    static int smem_set = 0;
    if (!smem_set) {
        cudaFuncSetAttribute(scan_cluster_kernel,
                             cudaFuncAttributeMaxDynamicSharedMemorySize,
                             SMEM_FLOATS * sizeof(float));
        cudaFuncSetAttribute(proj_mma_kernel,
                             cudaFuncAttributeMaxDynamicSharedMemorySize,
                             PROJ_SMEM_BYTES);
        smem_set = 1;
    }

    proj_mma_kernel<<<BT / 128, 512, PROJ_SMEM_BYTES>>>(x, Wz, Wr, Wh, bz, br, bh);
    scan_cluster_kernel<<<Bb, 512, SMEM_FLOATS * sizeof(float)>>>(Uz, Ur, Uh, out);
}